// round 1
// baseline (speedup 1.0000x reference)
#include <cuda_runtime.h>
#include <math.h>

#define NB 64
#define DD 768
#define HWS 1024
#define LL 8
#define MM 9
#define NCH 8
#define FSCALE 0.03608439182435161f
#define FEPS 1e-12f

// ---------------- scratch (no allocations allowed) ----------------
__device__ float g_cf[NB*DD], g_ct[NB*DD], g_c1[NB*DD], g_c2[NB*DD];
__device__ float g_qf[NB*DD], g_qt[NB*DD], g_qkf[NB*DD], g_qkt[NB*DD];
__device__ float g_biasf[NB], g_biast[NB], g_A[NB], g_B[NB];
__device__ float g_coef[NB*56];   // C0,V1..V6 each 8
__device__ float g_pvec[NB*24];   // pb[8], h1[8]=pfw*(1-pfw), h2[8]=pbfw*(1-pfw)
__device__ float g_att1[NB*HWS], g_att2[NB*HWS];
__device__ float g_w1[NB*HWS], g_w2[NB*HWS];
__device__ float g_g1[NB*HWS], g_g2[NB*HWS];
__device__ float g_sum1[NB], g_sum2[NB];
__device__ float g_extpart[2*NCH*NB*DD];
__device__ float g_e2[NB*DD], g_e2c1[NB*DD], g_e1c2[NB*DD], g_e2c2[NB*DD];
__device__ float g_P[6*NB*DD];

// ---------------- small fp32 GEMM: Y(64xDD) = X(64xDD) @ W (+bias), opt W^T ----
struct GemmDesc { const float* X; const float* W; const float* bias; float* Y; int transW; };
struct GemmBatch { GemmDesc d[6]; };

__global__ __launch_bounds__(256) void gemm_kernel(GemmBatch batch) {
    GemmDesc gd = batch.d[blockIdx.y];
    const int cb = blockIdx.x * 32;
    __shared__ float Xs[64][33];
    __shared__ float Ws[32][33];
    int tid = threadIdx.x;
    int cc = tid & 15;     // col pair
    int rr = tid >> 4;     // row group (4 rows)
    float acc00=0,acc01=0,acc10=0,acc11=0,acc20=0,acc21=0,acc30=0,acc31=0;
    for (int kb = 0; kb < DD; kb += 32) {
#pragma unroll
        for (int u = 0; u < 8; u++) {
            int i = tid + u*256;
            int r = i >> 5, k = i & 31;
            Xs[r][k] = gd.X[r*DD + kb + k];
        }
        if (gd.transW) {
#pragma unroll
            for (int u = 0; u < 4; u++) {
                int i = tid + u*256;
                int c = i >> 5, k = i & 31;
                Ws[k][c] = gd.W[(cb + c)*DD + kb + k];
            }
        } else {
#pragma unroll
            for (int u = 0; u < 4; u++) {
                int i = tid + u*256;
                int k = i >> 5, c = i & 31;
                Ws[k][c] = gd.W[(kb + k)*DD + cb + c];
            }
        }
        __syncthreads();
#pragma unroll
        for (int k = 0; k < 32; k++) {
            float w0 = Ws[k][cc*2], w1 = Ws[k][cc*2+1];
            float x0 = Xs[rr*4+0][k];
            float x1 = Xs[rr*4+1][k];
            float x2 = Xs[rr*4+2][k];
            float x3 = Xs[rr*4+3][k];
            acc00 += x0*w0; acc01 += x0*w1;
            acc10 += x1*w0; acc11 += x1*w1;
            acc20 += x2*w0; acc21 += x2*w1;
            acc30 += x3*w0; acc31 += x3*w1;
        }
        __syncthreads();
    }
    float b0 = 0.f, b1 = 0.f;
    if (gd.bias) { b0 = gd.bias[cb + cc*2]; b1 = gd.bias[cb + cc*2 + 1]; }
    int c0i = cb + cc*2;
    gd.Y[(rr*4+0)*DD + c0i]   = acc00 + b0; gd.Y[(rr*4+0)*DD + c0i+1] = acc01 + b1;
    gd.Y[(rr*4+1)*DD + c0i]   = acc10 + b0; gd.Y[(rr*4+1)*DD + c0i+1] = acc11 + b1;
    gd.Y[(rr*4+2)*DD + c0i]   = acc20 + b0; gd.Y[(rr*4+2)*DD + c0i+1] = acc21 + b1;
    gd.Y[(rr*4+3)*DD + c0i]   = acc30 + b0; gd.Y[(rr*4+3)*DD + c0i+1] = acc31 + b1;
}

// ---------------- per-n prep: pointer shifts, coefficient vectors, biases, ptr output ----
__global__ void prep_kernel(const float* __restrict__ module_prob,
                            const float* __restrict__ stack_ptr,
                            const float* __restrict__ find_kb,
                            const float* __restrict__ transform_kb,
                            float* __restrict__ out) {
    int n = blockIdx.x;
    int lane = threadIdx.x;
    float s1 = 0.f, s2 = 0.f;
    for (int j = lane; j < DD; j += 32) {
        s1 += g_qf[n*DD + j]*find_kb[j];
        s2 += g_qt[n*DD + j]*transform_kb[j];
    }
#pragma unroll
    for (int o = 16; o; o >>= 1) {
        s1 += __shfl_xor_sync(0xffffffffu, s1, o);
        s2 += __shfl_xor_sync(0xffffffffu, s2, o);
    }
    if (lane == 0) {
        g_biasf[n] = s1*FSCALE;
        g_biast[n] = s2*FSCALE;
        float ptr[LL], pfw[LL], pb[LL], pbfw[LL], p[MM];
        for (int l = 0; l < LL; l++) ptr[l] = stack_ptr[n*LL + l];
        for (int m = 0; m < MM; m++) p[m] = module_prob[n*MM + m];
        // move_fw
        pfw[0] = 0.f;
        for (int l = 1; l < LL; l++) pfw[l] = ptr[l-1];
        pfw[LL-1] += ptr[LL-1];
        // move_bw
        for (int l = 0; l < LL-1; l++) pb[l] = ptr[l+1];
        pb[LL-1] = 0.f; pb[0] += ptr[0];
        // move_bw(move_fw)
        for (int l = 0; l < LL-1; l++) pbfw[l] = pfw[l+1];
        pbfw[LL-1] = 0.f; pbfw[0] += pfw[0];
        float A = 0.f, Bv = 0.f;
        for (int l = 0; l < LL; l++) { A += pfw[l]*pfw[l]; Bv += pfw[l]*pbfw[l]; }
        g_A[n] = A; g_B[n] = Bv;
        // ptr_avg + softmax(/0.1)
        float pav[LL], mx = -1e30f;
        for (int l = 0; l < LL; l++) {
            pav[l] = (p[0]+p[2]+p[7])*ptr[l] + (p[1]+p[6])*pfw[l]
                   + p[3]*pbfw[l] + (p[4]+p[5]+p[8])*pb[l];
            mx = fmaxf(mx, pav[l]*10.0f);
        }
        float sm = 0.f, e[LL];
        for (int l = 0; l < LL; l++) { e[l] = expf(pav[l]*10.0f - mx); sm += e[l]; }
        for (int l = 0; l < LL; l++) out[NB*HWS*LL + n*LL + l] = e[l]/sm;
        // coefficient vectors
        for (int l = 0; l < LL; l++) {
            float c0 = p[0]+p[7]+p[8] + (p[1]+p[6])*(1.f-pfw[l]) + p[2]*(1.f-ptr[l])
                     + (p[4]+p[5])*(1.f-pb[l]) + p[3]*(1.f-pfw[l])*(1.f-pbfw[l]);
            g_coef[n*56 + 0*8 + l] = c0;
            g_coef[n*56 + 1*8 + l] = p[1]*pfw[l] + p[3]*pfw[l]*(1.f-pbfw[l]);
            g_coef[n*56 + 2*8 + l] = p[2]*ptr[l];
            g_coef[n*56 + 3*8 + l] = p[3]*pbfw[l];
            g_coef[n*56 + 4*8 + l] = p[4]*pb[l];
            g_coef[n*56 + 5*8 + l] = p[5]*pb[l];
            g_coef[n*56 + 6*8 + l] = p[6]*pfw[l];
            g_pvec[n*24 + l]      = pb[l];
            g_pvec[n*24 + 8 + l]  = pfw[l]*(1.f-pfw[l]);
            g_pvec[n*24 + 16 + l] = pbfw[l]*(1.f-pfw[l]);
        }
    }
}

// ---------------- phase B: stack reads + softmax weights ----------------
__device__ __forceinline__ float blk_red_max(float v, float* red) {
    int tid = threadIdx.x;
    red[tid] = v; __syncthreads();
    for (int o = 128; o; o >>= 1) { if (tid < o) red[tid] = fmaxf(red[tid], red[tid+o]); __syncthreads(); }
    float r = red[0]; __syncthreads();
    return r;
}
__device__ __forceinline__ float blk_red_sum(float v, float* red) {
    int tid = threadIdx.x;
    red[tid] = v; __syncthreads();
    for (int o = 128; o; o >>= 1) { if (tid < o) red[tid] += red[tid+o]; __syncthreads(); }
    float r = red[0]; __syncthreads();
    return r;
}

__global__ __launch_bounds__(256) void attn_kernel(const float* __restrict__ att_stack,
                                                   const float* __restrict__ stack_ptr) {
    int n = blockIdx.x, tid = threadIdx.x;
    __shared__ float red[256];
    float pb[LL], h1[LL], h2[LL], pt[LL];
#pragma unroll
    for (int l = 0; l < LL; l++) {
        pb[l] = g_pvec[n*24 + l];
        h1[l] = g_pvec[n*24 + 8 + l];
        h2[l] = g_pvec[n*24 + 16 + l];
        pt[l] = stack_ptr[n*LL + l];
    }
    float a1v[4], a2v[4];
    float m1 = -1e30f, m2 = -1e30f;
#pragma unroll
    for (int u = 0; u < 4; u++) {
        int s = tid + u*256;
        const float* Sr = att_stack + n*HWS*LL + s*LL;
        float4 lo = *(const float4*)Sr;
        float4 hi = *(const float4*)(Sr+4);
        float S[8] = {lo.x,lo.y,lo.z,lo.w,hi.x,hi.y,hi.z,hi.w};
        float a1 = 0.f, a2 = 0.f, gg1 = 0.f, gg2 = 0.f;
#pragma unroll
        for (int l = 0; l < 8; l++) {
            a1 += S[l]*pb[l]; a2 += S[l]*pt[l];
            gg1 += S[l]*h1[l]; gg2 += S[l]*h2[l];
        }
        g_att1[n*HWS+s] = a1; g_att2[n*HWS+s] = a2;
        g_g1[n*HWS+s] = gg1;  g_g2[n*HWS+s] = gg2;
        a1v[u] = a1; a2v[u] = a2;
        m1 = fmaxf(m1, a1); m2 = fmaxf(m2, a2);
    }
    float M1 = blk_red_max(m1, red);
    float M2 = blk_red_max(m2, red);
    float s1 = 0.f, s2 = 0.f;
#pragma unroll
    for (int u = 0; u < 4; u++) {
        int s = tid + u*256;
        float w1 = expf(a1v[u] - M1);
        float w2 = expf(a2v[u] - M2);
        g_w1[n*HWS+s] = w1; g_w2[n*HWS+s] = w2;
        s1 += w1; s2 += w2;
    }
    float S1 = blk_red_sum(s1, red);
    float S2 = blk_red_sum(s2, red);
    if (tid == 0) { g_sum1[n] = S1; g_sum2[n] = S2; }
}

// ---------------- phase C: single streaming pass over image_hidden ----------------
__global__ __launch_bounds__(256) void image_kernel(const float* __restrict__ image_hidden,
                                                    const float* __restrict__ image_mask,
                                                    const float* __restrict__ att_stack,
                                                    const float* __restrict__ scene_w,
                                                    const float* __restrict__ scene_b,
                                                    float* __restrict__ out) {
    int n = blockIdx.y;
    int chunk = blockIdx.x;
    int tid = threadIdx.x, lane = tid & 31, warp = tid >> 5;
    float qkf[24], qkt[24], scw[24];
#pragma unroll
    for (int j = 0; j < 24; j++) {
        qkf[j] = g_qkf[n*DD + lane + 32*j];
        qkt[j] = g_qkt[n*DD + lane + 32*j];
        scw[j] = scene_w[lane + 32*j];
    }
    float e1a[24], e2a[24];
#pragma unroll
    for (int j = 0; j < 24; j++) { e1a[j] = 0.f; e2a[j] = 0.f; }
    float biasf = g_biasf[n], biast = g_biast[n];
    float Av = g_A[n], Bv = g_B[n], scb = scene_b[0];
    float k0=0,k1=0,k2=0,k3=0,k4=0,k5=0,k6=0;
    if (lane < 8) {
        k0 = g_coef[n*56 + lane];      k1 = g_coef[n*56 + 8 + lane];
        k2 = g_coef[n*56 + 16 + lane]; k3 = g_coef[n*56 + 24 + lane];
        k4 = g_coef[n*56 + 32 + lane]; k5 = g_coef[n*56 + 40 + lane];
        k6 = g_coef[n*56 + 48 + lane];
    }
    for (int r = 0; r < 16; r++) {
        int s = chunk*128 + warp*16 + r;
        const float* img = image_hidden + (size_t)n*HWS*DD + (size_t)s*DD;
        float w1v = g_w1[n*HWS+s], w2v = g_w2[n*HWS+s];
        float a1 = g_att1[n*HWS+s], a2 = g_att2[n*HWS+s];
        float gg1 = g_g1[n*HWS+s], gg2 = g_g2[n*HWS+s];
        float n2 = 0.f, df = 0.f, dt = 0.f, dsc = 0.f;
#pragma unroll
        for (int j = 0; j < 24; j++) {
            float v = img[lane + 32*j];
            n2 += v*v; df += v*qkf[j]; dt += v*qkt[j]; dsc += v*scw[j];
            e1a[j] += w1v*v; e2a[j] += w2v*v;
        }
#pragma unroll
        for (int o = 16; o; o >>= 1) {
            n2  += __shfl_xor_sync(0xffffffffu, n2, o);
            df  += __shfl_xor_sync(0xffffffffu, df, o);
            dt  += __shfl_xor_sync(0xffffffffu, dt, o);
            dsc += __shfl_xor_sync(0xffffffffu, dsc, o);
        }
        float inv = 1.0f / fmaxf(sqrtf(n2), FEPS);
        float mk = image_mask[n*HWS + s];
        float sf = df*inv*FSCALE + biasf + mk;
        float st = dt*inv*FSCALE + biast + mk;
        float sc = dsc + scb;
        float a2f = sf*Av + gg1;
        float a1f = sf*Bv + gg2;
        float mf = fminf(a1f, a2f);
        float mn = fminf(a1, a2);
        float mx = fmaxf(a1, a2);
        if (lane < 8) {
            float Sv = att_stack[(size_t)n*HWS*LL + s*LL + lane];
            float o_v = Sv*k0 + sf*k1 + st*k2 + mf*k3 + mn*k4 + mx*k5 + sc*k6;
            out[(size_t)n*HWS*LL + s*LL + lane] = o_v;
        }
    }
    // deterministic cross-warp reduction of extract partials
    __shared__ float extsm[8*1536];
#pragma unroll
    for (int j = 0; j < 24; j++) {
        extsm[warp*1536 + lane + 32*j]       = e1a[j];
        extsm[warp*1536 + 768 + lane + 32*j] = e2a[j];
    }
    __syncthreads();
#pragma unroll
    for (int u = 0; u < 6; u++) {
        int idx = tid + u*256;            // [0,1536)
        float sum = 0.f;
#pragma unroll
        for (int w = 0; w < 8; w++) sum += extsm[w*1536 + idx];
        int e = (idx >= 768) ? 1 : 0;
        int d = idx - e*768;
        g_extpart[((e*NCH) + chunk)*NB*DD + n*DD + d] = sum;
    }
}

// ---------------- reduce extract partials, build mem GEMM inputs ----------------
__global__ void extreduce_kernel() {
    int n = blockIdx.x, tid = threadIdx.x;
    float inv1 = 1.0f / g_sum1[n];
    float inv2 = 1.0f / g_sum2[n];
#pragma unroll
    for (int u = 0; u < 3; u++) {
        int d = tid + u*256;
        float e1 = 0.f, e2 = 0.f;
#pragma unroll
        for (int c = 0; c < NCH; c++) {
            e1 += g_extpart[(0*NCH + c)*NB*DD + n*DD + d];
            e2 += g_extpart[(1*NCH + c)*NB*DD + n*DD + d];
        }
        e1 *= inv1; e2 *= inv2;
        float c1v = g_c1[n*DD + d], c2v = g_c2[n*DD + d];
        g_e2[n*DD + d]   = e2;
        g_e2c1[n*DD + d] = e2*c1v;
        g_e1c2[n*DD + d] = e1*c2v;
        g_e2c2[n*DD + d] = e2*c2v;
    }
}

// ---------------- final mem combine ----------------
__global__ void memcombine_kernel(const float* __restrict__ module_prob,
                                  const float* __restrict__ mem_prev,
                                  const float* __restrict__ d1b,
                                  const float* __restrict__ d2b,
                                  float* __restrict__ out) {
    int n = blockIdx.x, tid = threadIdx.x;
    float p0 = module_prob[n*MM + 0];
    float p7 = module_prob[n*MM + 7];
    float p8 = module_prob[n*MM + 8];
#pragma unroll
    for (int u = 0; u < 3; u++) {
        int d = tid + u*256;
        float m1 = g_P[0*NB*DD + n*DD + d] + g_P[1*NB*DD + n*DD + d] + g_P[2*NB*DD + n*DD + d] + d1b[d];
        float m2 = g_P[3*NB*DD + n*DD + d] + g_P[4*NB*DD + n*DD + d] + g_P[5*NB*DD + n*DD + d] + d2b[d];
        out[NB*HWS*LL + NB*LL + n*DD + d] = p0*mem_prev[n*DD + d] + p7*m1 + p8*m2;
    }
}

// ---------------- launch ----------------
extern "C" void kernel_launch(void* const* d_in, const int* in_sizes, int n_in,
                              void* d_out, int out_size) {
    (void)in_sizes; (void)n_in; (void)out_size;
    const float* control   = (const float*)d_in[0];
    const float* mprob     = (const float*)d_in[1];
    const float* mem_prev  = (const float*)d_in[2];
    const float* att_stack = (const float*)d_in[3];
    const float* stack_ptr = (const float*)d_in[4];
    const float* image_h   = (const float*)d_in[8];
    const float* image_m   = (const float*)d_in[9];
    const float* find_ci_w = (const float*)d_in[10];
    const float* find_ci_b = (const float*)d_in[11];
    const float* find_q_w  = (const float*)d_in[12];
    const float* find_q_b  = (const float*)d_in[13];
    const float* find_k_w  = (const float*)d_in[14];
    const float* find_k_b  = (const float*)d_in[15];
    const float* tr_ci_w   = (const float*)d_in[16];
    const float* tr_ci_b   = (const float*)d_in[17];
    const float* tr_q_w    = (const float*)d_in[18];
    const float* tr_q_b    = (const float*)d_in[19];
    const float* tr_k_w    = (const float*)d_in[20];
    const float* tr_k_b    = (const float*)d_in[21];
    const float* scene_w   = (const float*)d_in[22];
    const float* scene_b   = (const float*)d_in[23];
    const float* d1_ci_w   = (const float*)d_in[24];
    const float* d1_ci_b   = (const float*)d_in[25];
    const float* d1_mem_w  = (const float*)d_in[26];
    const float* d1_mem_b  = (const float*)d_in[27];
    const float* d2_ci_w   = (const float*)d_in[28];
    const float* d2_ci_b   = (const float*)d_in[29];
    const float* d2_mem_w  = (const float*)d_in[30];
    const float* d2_mem_b  = (const float*)d_in[31];
    float* out = (float*)d_out;

    float *p_cf, *p_ct, *p_c1, *p_c2, *p_qf, *p_qt, *p_qkf, *p_qkt;
    float *p_e2, *p_e2c1, *p_e1c2, *p_e2c2, *p_P;
    cudaGetSymbolAddress((void**)&p_cf,  g_cf);
    cudaGetSymbolAddress((void**)&p_ct,  g_ct);
    cudaGetSymbolAddress((void**)&p_c1,  g_c1);
    cudaGetSymbolAddress((void**)&p_c2,  g_c2);
    cudaGetSymbolAddress((void**)&p_qf,  g_qf);
    cudaGetSymbolAddress((void**)&p_qt,  g_qt);
    cudaGetSymbolAddress((void**)&p_qkf, g_qkf);
    cudaGetSymbolAddress((void**)&p_qkt, g_qkt);
    cudaGetSymbolAddress((void**)&p_e2,  g_e2);
    cudaGetSymbolAddress((void**)&p_e2c1, g_e2c1);
    cudaGetSymbolAddress((void**)&p_e1c2, g_e1c2);
    cudaGetSymbolAddress((void**)&p_e2c2, g_e2c2);
    cudaGetSymbolAddress((void**)&p_P,   g_P);

    // stage 1: cf, ct, c1, c2 = control @ {ci_w} + b
    GemmBatch b1 = {};
    b1.d[0] = {control, find_ci_w, find_ci_b, p_cf, 0};
    b1.d[1] = {control, tr_ci_w,   tr_ci_b,   p_ct, 0};
    b1.d[2] = {control, d1_ci_w,   d1_ci_b,   p_c1, 0};
    b1.d[3] = {control, d2_ci_w,   d2_ci_b,   p_c2, 0};
    gemm_kernel<<<dim3(24,4), 256>>>(b1);

    // stage 2: qf = cf@find_q_w+b ; qt = ct@tr_q_w+b
    GemmBatch b2 = {};
    b2.d[0] = {p_cf, find_q_w, find_q_b, p_qf, 0};
    b2.d[1] = {p_ct, tr_q_w,   tr_q_b,   p_qt, 0};
    gemm_kernel<<<dim3(24,2), 256>>>(b2);

    // stage 3: qkf = qf @ find_k_w^T ; qkt = qt @ tr_k_w^T
    GemmBatch b3 = {};
    b3.d[0] = {p_qf, find_k_w, nullptr, p_qkf, 1};
    b3.d[1] = {p_qt, tr_k_w,   nullptr, p_qkt, 1};
    gemm_kernel<<<dim3(24,2), 256>>>(b3);

    prep_kernel<<<NB, 32>>>(mprob, stack_ptr, find_k_b, tr_k_b, out);
    attn_kernel<<<NB, 256>>>(att_stack, stack_ptr);
    image_kernel<<<dim3(NCH, NB), 256>>>(image_h, image_m, att_stack, scene_w, scene_b, out);
    extreduce_kernel<<<NB, 256>>>();

    // mem gemms: 6 partials
    GemmBatch b4 = {};
    b4.d[0] = {control, d1_mem_w,              nullptr, p_P + 0*NB*DD, 0};
    b4.d[1] = {p_e2,    d1_mem_w + 768*768,    nullptr, p_P + 1*NB*DD, 0};
    b4.d[2] = {p_e2c1,  d1_mem_w + 2*768*768,  nullptr, p_P + 2*NB*DD, 0};
    b4.d[3] = {control, d2_mem_w,              nullptr, p_P + 3*NB*DD, 0};
    b4.d[4] = {p_e1c2,  d2_mem_w + 768*768,    nullptr, p_P + 4*NB*DD, 0};
    b4.d[5] = {p_e2c2,  d2_mem_w + 2*768*768,  nullptr, p_P + 5*NB*DD, 0};
    gemm_kernel<<<dim3(24,6), 256>>>(b4);

    memcombine_kernel<<<NB, 256>>>(mprob, mem_prev, d1_mem_b, d2_mem_b, out);
}

// round 2
// speedup vs baseline: 1.5127x; 1.5127x over previous
#include <cuda_runtime.h>
#include <math.h>

#define NB 64
#define DD 768
#define HWS 1024
#define LL 8
#define MM 9
#define NCH 8
#define SPL 3
#define FSCALE 0.03608439182435161f
#define FEPS 1e-12f

// ---------------- scratch ----------------
__device__ float g_cf[SPL*NB*DD], g_ct[SPL*NB*DD], g_c1[SPL*NB*DD], g_c2[SPL*NB*DD];
__device__ float g_qf[SPL*NB*DD], g_qt[SPL*NB*DD], g_qkf[SPL*NB*DD], g_qkt[SPL*NB*DD];
__device__ float g_biasf[NB], g_biast[NB], g_A[NB], g_B[NB];
__device__ float g_coef[NB*56];
__device__ float g_att1[NB*HWS], g_att2[NB*HWS];
__device__ float g_w1[NB*HWS], g_w2[NB*HWS];
__device__ float g_g1[NB*HWS], g_g2[NB*HWS];
__device__ float g_sum1[NB], g_sum2[NB];
__device__ float g_extpart[2*NCH*NB*DD];
__device__ float g_e2[NB*DD], g_e2c1[NB*DD], g_e1c2[NB*DD], g_e2c2[NB*DD];
__device__ float g_P[6*NB*DD];

// ---------------- GEMM v2: Y(64xDD) = X@W (+bias), reg-tiled, K-split ----------------
// block: 256 threads, tile 64 rows x 32 cols, thread tile 2x4.
// grid: (24 colblocks, ndesc, nsplit)
struct G2Desc { const float* x0; const float* x1; const float* x2;
                const float* w; const float* bias; float* y; int transW; };
struct G2Batch { G2Desc d[6]; int nsplit; int nx; };

__global__ __launch_bounds__(256) void gemm2_kernel(G2Batch batch) {
    G2Desc gd = batch.d[blockIdx.y];
    const int split = blockIdx.z;
    const int klen = DD / batch.nsplit;
    const int k0 = split * klen;
    const int cb = blockIdx.x * 32;
    const int nx = batch.nx;

    __shared__ float sX[16*66];   // k-major, padded
    __shared__ float sW[16*36];   // k-major, padded

    int tid = threadIdx.x;
    int rg = tid >> 3;    // 0..31 : 2 rows each
    int cg = tid & 7;     // 0..7  : 4 cols each
    float a00=0,a01=0,a02=0,a03=0,a10=0,a11=0,a12=0,a13=0;

    const int rX = tid >> 2;      // 0..63
    const int kq = tid & 3;       // 0..3

    for (int kk = 0; kk < klen; kk += 16) {
        // --- fill X (k-major, transposed store, conflict-free via pad 66) ---
        {
            int off = rX*DD + k0 + kk + kq*4;
            float4 xv = *(const float4*)(gd.x0 + off);
            if (nx == 3) {
                float4 b = *(const float4*)(gd.x1 + off);
                float4 c = *(const float4*)(gd.x2 + off);
                xv.x += b.x + c.x; xv.y += b.y + c.y;
                xv.z += b.z + c.z; xv.w += b.w + c.w;
            }
            sX[(kq*4+0)*66 + rX] = xv.x;
            sX[(kq*4+1)*66 + rX] = xv.y;
            sX[(kq*4+2)*66 + rX] = xv.z;
            sX[(kq*4+3)*66 + rX] = xv.w;
        }
        // --- fill W (k-major) ---
        if (!gd.transW) {
            int kw = tid >> 4;            // 0..15
            int cw = (tid & 15) * 2;      // 0..30
            float2 wv = *(const float2*)(gd.w + (size_t)(k0+kk+kw)*DD + cb + cw);
            sW[kw*36 + cw]   = wv.x;
            sW[kw*36 + cw+1] = wv.y;
        } else {
            int cw = tid >> 3;            // 0..31
            int kw = (tid & 7) * 2;       // 0..14
            float2 wv = *(const float2*)(gd.w + (size_t)(cb+cw)*DD + k0+kk+kw);
            sW[kw*36 + cw]     = wv.x;
            sW[(kw+1)*36 + cw] = wv.y;
        }
        __syncthreads();
#pragma unroll
        for (int k = 0; k < 16; k++) {
            float2 xv = *(const float2*)&sX[k*66 + rg*2];
            float4 wv = *(const float4*)&sW[k*36 + cg*4];
            a00 += xv.x*wv.x; a01 += xv.x*wv.y; a02 += xv.x*wv.z; a03 += xv.x*wv.w;
            a10 += xv.y*wv.x; a11 += xv.y*wv.y; a12 += xv.y*wv.z; a13 += xv.y*wv.w;
        }
        __syncthreads();
    }
    float4 bv = {0.f,0.f,0.f,0.f};
    if (split == 0 && gd.bias) bv = *(const float4*)(gd.bias + cb + cg*4);
    float* y = gd.y + (size_t)split*NB*DD;
    float4 o0 = {a00+bv.x, a01+bv.y, a02+bv.z, a03+bv.w};
    float4 o1 = {a10+bv.x, a11+bv.y, a12+bv.z, a13+bv.w};
    *(float4*)(y + (rg*2+0)*DD + cb + cg*4) = o0;
    *(float4*)(y + (rg*2+1)*DD + cb + cg*4) = o1;
}

// ---------------- block reductions ----------------
__device__ __forceinline__ float blk_red_max(float v, float* red) {
    int tid = threadIdx.x;
    red[tid] = v; __syncthreads();
    for (int o = 128; o; o >>= 1) { if (tid < o) red[tid] = fmaxf(red[tid], red[tid+o]); __syncthreads(); }
    float r = red[0]; __syncthreads();
    return r;
}
__device__ __forceinline__ float blk_red_sum(float v, float* red) {
    int tid = threadIdx.x;
    red[tid] = v; __syncthreads();
    for (int o = 128; o; o >>= 1) { if (tid < o) red[tid] += red[tid+o]; __syncthreads(); }
    float r = red[0]; __syncthreads();
    return r;
}

// ---------------- attn + prep (merged) ----------------
__global__ __launch_bounds__(256) void attn_prep_kernel(const float* __restrict__ module_prob,
                                                        const float* __restrict__ stack_ptr,
                                                        const float* __restrict__ find_kb,
                                                        const float* __restrict__ transform_kb,
                                                        const float* __restrict__ att_stack,
                                                        float* __restrict__ out) {
    int n = blockIdx.x, tid = threadIdx.x;
    __shared__ float red[256];
    __shared__ float s_pvec[24];

    // bias dots over qf/qt (sum of 3 K-split partials)
    float s1 = 0.f, s2 = 0.f;
    for (int j = tid; j < DD; j += 256) {
        float qv = g_qf[n*DD+j] + g_qf[NB*DD + n*DD+j] + g_qf[2*NB*DD + n*DD+j];
        float tv = g_qt[n*DD+j] + g_qt[NB*DD + n*DD+j] + g_qt[2*NB*DD + n*DD+j];
        s1 += qv*find_kb[j]; s2 += tv*transform_kb[j];
    }
    float S1 = blk_red_sum(s1, red);
    float S2 = blk_red_sum(s2, red);
    if (tid == 0) { g_biasf[n] = S1*FSCALE; g_biast[n] = S2*FSCALE; }

    if (tid == 0) {
        float ptr[LL], pfw[LL], pb[LL], pbfw[LL], p[MM];
        for (int l = 0; l < LL; l++) ptr[l] = stack_ptr[n*LL + l];
        for (int m = 0; m < MM; m++) p[m] = module_prob[n*MM + m];
        pfw[0] = 0.f;
        for (int l = 1; l < LL; l++) pfw[l] = ptr[l-1];
        pfw[LL-1] += ptr[LL-1];
        for (int l = 0; l < LL-1; l++) pb[l] = ptr[l+1];
        pb[LL-1] = 0.f; pb[0] += ptr[0];
        for (int l = 0; l < LL-1; l++) pbfw[l] = pfw[l+1];
        pbfw[LL-1] = 0.f; pbfw[0] += pfw[0];
        float A = 0.f, Bv = 0.f;
        for (int l = 0; l < LL; l++) { A += pfw[l]*pfw[l]; Bv += pfw[l]*pbfw[l]; }
        g_A[n] = A; g_B[n] = Bv;
        float pav[LL], mx = -1e30f;
        for (int l = 0; l < LL; l++) {
            pav[l] = (p[0]+p[2]+p[7])*ptr[l] + (p[1]+p[6])*pfw[l]
                   + p[3]*pbfw[l] + (p[4]+p[5]+p[8])*pb[l];
            mx = fmaxf(mx, pav[l]*10.0f);
        }
        float sm = 0.f, e[LL];
        for (int l = 0; l < LL; l++) { e[l] = expf(pav[l]*10.0f - mx); sm += e[l]; }
        for (int l = 0; l < LL; l++) out[NB*HWS*LL + n*LL + l] = e[l]/sm;
        for (int l = 0; l < LL; l++) {
            float c0 = p[0]+p[7]+p[8] + (p[1]+p[6])*(1.f-pfw[l]) + p[2]*(1.f-ptr[l])
                     + (p[4]+p[5])*(1.f-pb[l]) + p[3]*(1.f-pfw[l])*(1.f-pbfw[l]);
            g_coef[n*56 + 0*8 + l] = c0;
            g_coef[n*56 + 1*8 + l] = p[1]*pfw[l] + p[3]*pfw[l]*(1.f-pbfw[l]);
            g_coef[n*56 + 2*8 + l] = p[2]*ptr[l];
            g_coef[n*56 + 3*8 + l] = p[3]*pbfw[l];
            g_coef[n*56 + 4*8 + l] = p[4]*pb[l];
            g_coef[n*56 + 5*8 + l] = p[5]*pb[l];
            g_coef[n*56 + 6*8 + l] = p[6]*pfw[l];
            s_pvec[l]      = pb[l];
            s_pvec[8 + l]  = pfw[l]*(1.f-pfw[l]);
            s_pvec[16 + l] = pbfw[l]*(1.f-pfw[l]);
        }
    }
    __syncthreads();

    float pb[LL], h1[LL], h2[LL], pt[LL];
#pragma unroll
    for (int l = 0; l < LL; l++) {
        pb[l] = s_pvec[l];
        h1[l] = s_pvec[8 + l];
        h2[l] = s_pvec[16 + l];
        pt[l] = stack_ptr[n*LL + l];
    }
    float a1v[4], a2v[4];
    float m1 = -1e30f, m2 = -1e30f;
#pragma unroll
    for (int u = 0; u < 4; u++) {
        int s = tid + u*256;
        const float* Sr = att_stack + (size_t)n*HWS*LL + s*LL;
        float4 lo = *(const float4*)Sr;
        float4 hi = *(const float4*)(Sr+4);
        float S[8] = {lo.x,lo.y,lo.z,lo.w,hi.x,hi.y,hi.z,hi.w};
        float a1 = 0.f, a2 = 0.f, gg1 = 0.f, gg2 = 0.f;
#pragma unroll
        for (int l = 0; l < 8; l++) {
            a1 += S[l]*pb[l]; a2 += S[l]*pt[l];
            gg1 += S[l]*h1[l]; gg2 += S[l]*h2[l];
        }
        g_att1[n*HWS+s] = a1; g_att2[n*HWS+s] = a2;
        g_g1[n*HWS+s] = gg1;  g_g2[n*HWS+s] = gg2;
        a1v[u] = a1; a2v[u] = a2;
        m1 = fmaxf(m1, a1); m2 = fmaxf(m2, a2);
    }
    float M1 = blk_red_max(m1, red);
    float M2 = blk_red_max(m2, red);
    float t1 = 0.f, t2 = 0.f;
#pragma unroll
    for (int u = 0; u < 4; u++) {
        int s = tid + u*256;
        float w1 = expf(a1v[u] - M1);
        float w2 = expf(a2v[u] - M2);
        g_w1[n*HWS+s] = w1; g_w2[n*HWS+s] = w2;
        t1 += w1; t2 += w2;
    }
    float T1 = blk_red_sum(t1, red);
    float T2 = blk_red_sum(t2, red);
    if (tid == 0) { g_sum1[n] = T1; g_sum2[n] = T2; }
}

// ---------------- image pass: float4 + 2-row interleave ----------------
__global__ __launch_bounds__(256) void image_kernel(const float* __restrict__ image_hidden,
                                                    const float* __restrict__ image_mask,
                                                    const float* __restrict__ att_stack,
                                                    const float* __restrict__ scene_w,
                                                    const float* __restrict__ scene_b,
                                                    float* __restrict__ out) {
    int n = blockIdx.y;
    int chunk = blockIdx.x;
    int tid = threadIdx.x, lane = tid & 31, warp = tid >> 5;

    const float4* q0 = (const float4*)(g_qkf + n*DD);
    const float4* q1 = (const float4*)(g_qkf + NB*DD + n*DD);
    const float4* q2 = (const float4*)(g_qkf + 2*NB*DD + n*DD);
    const float4* t0 = (const float4*)(g_qkt + n*DD);
    const float4* t1p = (const float4*)(g_qkt + NB*DD + n*DD);
    const float4* t2p = (const float4*)(g_qkt + 2*NB*DD + n*DD);
    const float4* sw4 = (const float4*)scene_w;

    float4 qkf[6], qkt[6], scw[6], e1[6], e2[6];
#pragma unroll
    for (int j = 0; j < 6; j++) {
        int idx = lane + j*32;
        float4 a = q0[idx], b = q1[idx], c = q2[idx];
        qkf[j] = make_float4(a.x+b.x+c.x, a.y+b.y+c.y, a.z+b.z+c.z, a.w+b.w+c.w);
        a = t0[idx]; b = t1p[idx]; c = t2p[idx];
        qkt[j] = make_float4(a.x+b.x+c.x, a.y+b.y+c.y, a.z+b.z+c.z, a.w+b.w+c.w);
        scw[j] = sw4[idx];
        e1[j] = make_float4(0.f,0.f,0.f,0.f);
        e2[j] = make_float4(0.f,0.f,0.f,0.f);
    }
    float biasf = g_biasf[n], biast = g_biast[n];
    float Av = g_A[n], Bv = g_B[n], scb = scene_b[0];
    float k0=0,k1=0,k2=0,k3=0,k4=0,k5=0,k6=0;
    if (lane < 8) {
        k0 = g_coef[n*56 + lane];      k1 = g_coef[n*56 + 8 + lane];
        k2 = g_coef[n*56 + 16 + lane]; k3 = g_coef[n*56 + 24 + lane];
        k4 = g_coef[n*56 + 32 + lane]; k5 = g_coef[n*56 + 40 + lane];
        k6 = g_coef[n*56 + 48 + lane];
    }

    for (int rp = 0; rp < 8; rp++) {
        int s0 = chunk*128 + warp*16 + rp*2;
        int s1 = s0 + 1;
        const float4* i0 = (const float4*)(image_hidden + ((size_t)n*HWS + s0)*DD) + lane;
        const float4* i1 = (const float4*)(image_hidden + ((size_t)n*HWS + s1)*DD) + lane;
        float4 v0[6], v1[6];
#pragma unroll
        for (int j = 0; j < 6; j++) v0[j] = __ldcs(i0 + j*32);
#pragma unroll
        for (int j = 0; j < 6; j++) v1[j] = __ldcs(i1 + j*32);

        float w1a = g_w1[n*HWS+s0], w2a = g_w2[n*HWS+s0];
        float w1b = g_w1[n*HWS+s1], w2b = g_w2[n*HWS+s1];

        float n2a=0,dfa=0,dta=0,dsa=0,n2b=0,dfb=0,dtb=0,dsb=0;
#pragma unroll
        for (int j = 0; j < 6; j++) {
            float4 a = v0[j], b = v1[j];
            n2a += a.x*a.x + a.y*a.y + a.z*a.z + a.w*a.w;
            n2b += b.x*b.x + b.y*b.y + b.z*b.z + b.w*b.w;
            dfa += a.x*qkf[j].x + a.y*qkf[j].y + a.z*qkf[j].z + a.w*qkf[j].w;
            dfb += b.x*qkf[j].x + b.y*qkf[j].y + b.z*qkf[j].z + b.w*qkf[j].w;
            dta += a.x*qkt[j].x + a.y*qkt[j].y + a.z*qkt[j].z + a.w*qkt[j].w;
            dtb += b.x*qkt[j].x + b.y*qkt[j].y + b.z*qkt[j].z + b.w*qkt[j].w;
            dsa += a.x*scw[j].x + a.y*scw[j].y + a.z*scw[j].z + a.w*scw[j].w;
            dsb += b.x*scw[j].x + b.y*scw[j].y + b.z*scw[j].z + b.w*scw[j].w;
            e1[j].x += w1a*a.x + w1b*b.x; e1[j].y += w1a*a.y + w1b*b.y;
            e1[j].z += w1a*a.z + w1b*b.z; e1[j].w += w1a*a.w + w1b*b.w;
            e2[j].x += w2a*a.x + w2b*b.x; e2[j].y += w2a*a.y + w2b*b.y;
            e2[j].z += w2a*a.z + w2b*b.z; e2[j].w += w2a*a.w + w2b*b.w;
        }
#pragma unroll
        for (int o = 16; o; o >>= 1) {
            n2a += __shfl_xor_sync(0xffffffffu, n2a, o);
            n2b += __shfl_xor_sync(0xffffffffu, n2b, o);
            dfa += __shfl_xor_sync(0xffffffffu, dfa, o);
            dfb += __shfl_xor_sync(0xffffffffu, dfb, o);
            dta += __shfl_xor_sync(0xffffffffu, dta, o);
            dtb += __shfl_xor_sync(0xffffffffu, dtb, o);
            dsa += __shfl_xor_sync(0xffffffffu, dsa, o);
            dsb += __shfl_xor_sync(0xffffffffu, dsb, o);
        }
        // row s0
        {
            float inv = 1.0f / fmaxf(sqrtf(n2a), FEPS);
            float mk = image_mask[n*HWS + s0];
            float sf = dfa*inv*FSCALE + biasf + mk;
            float st = dta*inv*FSCALE + biast + mk;
            float sc = dsa + scb;
            float a1 = g_att1[n*HWS+s0], a2 = g_att2[n*HWS+s0];
            float gg1 = g_g1[n*HWS+s0], gg2 = g_g2[n*HWS+s0];
            float a2f = sf*Av + gg1;
            float a1f = sf*Bv + gg2;
            float mf = fminf(a1f, a2f);
            float mn = fminf(a1, a2);
            float mx = fmaxf(a1, a2);
            if (lane < 8) {
                float Sv = att_stack[((size_t)n*HWS + s0)*LL + lane];
                out[((size_t)n*HWS + s0)*LL + lane] =
                    Sv*k0 + sf*k1 + st*k2 + mf*k3 + mn*k4 + mx*k5 + sc*k6;
            }
        }
        // row s1
        {
            float inv = 1.0f / fmaxf(sqrtf(n2b), FEPS);
            float mk = image_mask[n*HWS + s1];
            float sf = dfb*inv*FSCALE + biasf + mk;
            float st = dtb*inv*FSCALE + biast + mk;
            float sc = dsb + scb;
            float a1 = g_att1[n*HWS+s1], a2 = g_att2[n*HWS+s1];
            float gg1 = g_g1[n*HWS+s1], gg2 = g_g2[n*HWS+s1];
            float a2f = sf*Av + gg1;
            float a1f = sf*Bv + gg2;
            float mf = fminf(a1f, a2f);
            float mn = fminf(a1, a2);
            float mx = fmaxf(a1, a2);
            if (lane < 8) {
                float Sv = att_stack[((size_t)n*HWS + s1)*LL + lane];
                out[((size_t)n*HWS + s1)*LL + lane] =
                    Sv*k0 + sf*k1 + st*k2 + mf*k3 + mn*k4 + mx*k5 + sc*k6;
            }
        }
    }
    // deterministic cross-warp reduction of extract partials
    __shared__ float extsm[8*1536];
    float4* my1 = (float4*)&extsm[warp*1536];
    float4* my2 = (float4*)&extsm[warp*1536 + 768];
#pragma unroll
    for (int j = 0; j < 6; j++) {
        my1[lane + j*32] = e1[j];
        my2[lane + j*32] = e2[j];
    }
    __syncthreads();
#pragma unroll
    for (int u = 0; u < 6; u++) {
        int idx = tid + u*256;
        float sum = 0.f;
#pragma unroll
        for (int w = 0; w < 8; w++) sum += extsm[w*1536 + idx];
        int e = (idx >= 768) ? 1 : 0;
        int d = idx - e*768;
        g_extpart[((e*NCH) + chunk)*NB*DD + n*DD + d] = sum;
    }
}

// ---------------- reduce extract partials (c1/c2 are 3-way K-split) ----------------
__global__ void extreduce_kernel() {
    int n = blockIdx.x, tid = threadIdx.x;
    int d = blockIdx.y*256 + tid;
    float inv1 = 1.0f / g_sum1[n];
    float inv2 = 1.0f / g_sum2[n];
    float e1 = 0.f, e2 = 0.f;
#pragma unroll
    for (int c = 0; c < NCH; c++) {
        e1 += g_extpart[(0*NCH + c)*NB*DD + n*DD + d];
        e2 += g_extpart[(1*NCH + c)*NB*DD + n*DD + d];
    }
    e1 *= inv1; e2 *= inv2;
    float c1v = g_c1[n*DD + d] + g_c1[NB*DD + n*DD + d] + g_c1[2*NB*DD + n*DD + d];
    float c2v = g_c2[n*DD + d] + g_c2[NB*DD + n*DD + d] + g_c2[2*NB*DD + n*DD + d];
    g_e2[n*DD + d]   = e2;
    g_e2c1[n*DD + d] = e2*c1v;
    g_e1c2[n*DD + d] = e1*c2v;
    g_e2c2[n*DD + d] = e2*c2v;
}

// ---------------- final mem combine ----------------
__global__ void memcombine_kernel(const float* __restrict__ module_prob,
                                  const float* __restrict__ mem_prev,
                                  const float* __restrict__ d1b,
                                  const float* __restrict__ d2b,
                                  float* __restrict__ out) {
    int n = blockIdx.x, tid = threadIdx.x;
    int d = blockIdx.y*256 + tid;
    float p0 = module_prob[n*MM + 0];
    float p7 = module_prob[n*MM + 7];
    float p8 = module_prob[n*MM + 8];
    float m1 = g_P[0*NB*DD + n*DD + d] + g_P[1*NB*DD + n*DD + d] + g_P[2*NB*DD + n*DD + d] + d1b[d];
    float m2 = g_P[3*NB*DD + n*DD + d] + g_P[4*NB*DD + n*DD + d] + g_P[5*NB*DD + n*DD + d] + d2b[d];
    out[NB*HWS*LL + NB*LL + n*DD + d] = p0*mem_prev[n*DD + d] + p7*m1 + p8*m2;
}

// ---------------- launch ----------------
extern "C" void kernel_launch(void* const* d_in, const int* in_sizes, int n_in,
                              void* d_out, int out_size) {
    (void)in_sizes; (void)n_in; (void)out_size;
    const float* control   = (const float*)d_in[0];
    const float* mprob     = (const float*)d_in[1];
    const float* mem_prev  = (const float*)d_in[2];
    const float* att_stack = (const float*)d_in[3];
    const float* stack_ptr = (const float*)d_in[4];
    const float* image_h   = (const float*)d_in[8];
    const float* image_m   = (const float*)d_in[9];
    const float* find_ci_w = (const float*)d_in[10];
    const float* find_ci_b = (const float*)d_in[11];
    const float* find_q_w  = (const float*)d_in[12];
    const float* find_q_b  = (const float*)d_in[13];
    const float* find_k_w  = (const float*)d_in[14];
    const float* find_k_b  = (const float*)d_in[15];
    const float* tr_ci_w   = (const float*)d_in[16];
    const float* tr_ci_b   = (const float*)d_in[17];
    const float* tr_q_w    = (const float*)d_in[18];
    const float* tr_q_b    = (const float*)d_in[19];
    const float* tr_k_w    = (const float*)d_in[20];
    const float* tr_k_b    = (const float*)d_in[21];
    const float* scene_w   = (const float*)d_in[22];
    const float* scene_b   = (const float*)d_in[23];
    const float* d1_ci_w   = (const float*)d_in[24];
    const float* d1_ci_b   = (const float*)d_in[25];
    const float* d1_mem_w  = (const float*)d_in[26];
    const float* d1_mem_b  = (const float*)d_in[27];
    const float* d2_ci_w   = (const float*)d_in[28];
    const float* d2_ci_b   = (const float*)d_in[29];
    const float* d2_mem_w  = (const float*)d_in[30];
    const float* d2_mem_b  = (const float*)d_in[31];
    float* out = (float*)d_out;

    float *p_cf, *p_ct, *p_c1, *p_c2, *p_qf, *p_qt, *p_qkf, *p_qkt;
    float *p_e2, *p_e2c1, *p_e1c2, *p_e2c2, *p_P;
    cudaGetSymbolAddress((void**)&p_cf,  g_cf);
    cudaGetSymbolAddress((void**)&p_ct,  g_ct);
    cudaGetSymbolAddress((void**)&p_c1,  g_c1);
    cudaGetSymbolAddress((void**)&p_c2,  g_c2);
    cudaGetSymbolAddress((void**)&p_qf,  g_qf);
    cudaGetSymbolAddress((void**)&p_qt,  g_qt);
    cudaGetSymbolAddress((void**)&p_qkf, g_qkf);
    cudaGetSymbolAddress((void**)&p_qkt, g_qkt);
    cudaGetSymbolAddress((void**)&p_e2,  g_e2);
    cudaGetSymbolAddress((void**)&p_e2c1, g_e2c1);
    cudaGetSymbolAddress((void**)&p_e1c2, g_e1c2);
    cudaGetSymbolAddress((void**)&p_e2c2, g_e2c2);
    cudaGetSymbolAddress((void**)&p_P,   g_P);

    const int ND = NB*DD;

    // stage 1: cf, ct, c1, c2 = control @ {ci_w} + b   (K-split 3)
    G2Batch b1 = {};
    b1.nsplit = SPL; b1.nx = 1;
    b1.d[0] = {control, nullptr, nullptr, find_ci_w, find_ci_b, p_cf, 0};
    b1.d[1] = {control, nullptr, nullptr, tr_ci_w,   tr_ci_b,   p_ct, 0};
    b1.d[2] = {control, nullptr, nullptr, d1_ci_w,   d1_ci_b,   p_c1, 0};
    b1.d[3] = {control, nullptr, nullptr, d2_ci_w,   d2_ci_b,   p_c2, 0};
    gemm2_kernel<<<dim3(24,4,SPL), 256>>>(b1);

    // stage 2: qf = (cf)@find_q_w + b ; qt  (X = 3 partials, K-split 3)
    G2Batch b2 = {};
    b2.nsplit = SPL; b2.nx = 3;
    b2.d[0] = {p_cf, p_cf+ND, p_cf+2*ND, find_q_w, find_q_b, p_qf, 0};
    b2.d[1] = {p_ct, p_ct+ND, p_ct+2*ND, tr_q_w,   tr_q_b,   p_qt, 0};
    gemm2_kernel<<<dim3(24,2,SPL), 256>>>(b2);

    // stage 3: qkf = qf @ find_k_w^T ; qkt  (transW, K-split 3)
    G2Batch b3 = {};
    b3.nsplit = SPL; b3.nx = 3;
    b3.d[0] = {p_qf, p_qf+ND, p_qf+2*ND, find_k_w, nullptr, p_qkf, 1};
    b3.d[1] = {p_qt, p_qt+ND, p_qt+2*ND, tr_k_w,   nullptr, p_qkt, 1};
    gemm2_kernel<<<dim3(24,2,SPL), 256>>>(b3);

    attn_prep_kernel<<<NB, 256>>>(mprob, stack_ptr, find_k_b, tr_k_b, att_stack, out);
    image_kernel<<<dim3(NCH, NB), 256>>>(image_h, image_m, att_stack, scene_w, scene_b, out);
    extreduce_kernel<<<dim3(NB,3), 256>>>();

    // stage 4: 6 mem partials (no split; X single)
    G2Batch b4 = {};
    b4.nsplit = 1; b4.nx = 1;
    b4.d[0] = {control, nullptr, nullptr, d1_mem_w,             nullptr, p_P + 0*ND, 0};
    b4.d[1] = {p_e2,    nullptr, nullptr, d1_mem_w + DD*DD,     nullptr, p_P + 1*ND, 0};
    b4.d[2] = {p_e2c1,  nullptr, nullptr, d1_mem_w + 2*DD*DD,   nullptr, p_P + 2*ND, 0};
    b4.d[3] = {control, nullptr, nullptr, d2_mem_w,             nullptr, p_P + 3*ND, 0};
    b4.d[4] = {p_e1c2,  nullptr, nullptr, d2_mem_w + DD*DD,     nullptr, p_P + 4*ND, 0};
    b4.d[5] = {p_e2c2,  nullptr, nullptr, d2_mem_w + 2*DD*DD,   nullptr, p_P + 5*ND, 0};
    gemm2_kernel<<<dim3(24,6,1), 256>>>(b4);

    memcombine_kernel<<<dim3(NB,3), 256>>>(mprob, mem_prev, d1_mem_b, d2_mem_b, out);
}

// round 3
// speedup vs baseline: 1.6103x; 1.0645x over previous
#include <cuda_runtime.h>
#include <math.h>

#define NB 64
#define DD 768
#define HWS 1024
#define LL 8
#define MM 9
#define NCH 8
#define SPL 3
#define KSTEP 32
#define FSCALE 0.03608439182435161f
#define FEPS 1e-12f

// ---------------- scratch ----------------
__device__ float g_cf[SPL*NB*DD], g_ct[SPL*NB*DD], g_c1[SPL*NB*DD], g_c2[SPL*NB*DD];
__device__ float g_qf[SPL*NB*DD], g_qt[SPL*NB*DD], g_qkf[SPL*NB*DD], g_qkt[SPL*NB*DD];
__device__ float g_biasf[NB], g_biast[NB], g_A[NB], g_B[NB];
__device__ float g_coef[NB*56];
__device__ float g_att1[NB*HWS], g_att2[NB*HWS];
__device__ float g_w1[NB*HWS], g_w2[NB*HWS];
__device__ float g_g1[NB*HWS], g_g2[NB*HWS];
__device__ float g_sum1[NB], g_sum2[NB];
__device__ float g_extpart[2*NCH*NB*DD];
__device__ float g_e2[NB*DD], g_e2c1[NB*DD], g_e1c2[NB*DD], g_e2c2[NB*DD];
__device__ float g_P[6*NB*DD];

// ---------------- GEMM v3: double-buffered, KSTEP=32 ----------------
struct G2Desc { const float* x0; const float* x1; const float* x2;
                const float* w; const float* bias; float* y; int transW; };
struct G2Batch { G2Desc d[6]; int nsplit; int nx; };

__global__ __launch_bounds__(256) void gemm3_kernel(G2Batch batch) {
    G2Desc gd = batch.d[blockIdx.y];
    const int split = blockIdx.z;
    const int klen = DD / batch.nsplit;
    const int k0 = split * klen;
    const int cb = blockIdx.x * 32;
    const int nx = batch.nx;
    const int niter = klen / KSTEP;

    __shared__ float sX[2][KSTEP*66];
    __shared__ float sW[2][KSTEP*36];

    const int tid = threadIdx.x;
    const int rg = tid >> 3;        // 0..31, 2 rows each
    const int cg = tid & 7;         // 0..7, 4 cols each
    const int rX = tid >> 2;        // 0..63
    const int kq = tid & 3;         // 0..3
    // W mappings
    const int kwN = tid >> 3;            // non-trans: 0..31 row
    const int cwN = (tid & 7) * 4;       // non-trans: col
    const int cwT = tid >> 3;            // trans: 0..31 col
    const int kwT = (tid & 7) * 4;       // trans: k

    float4 xr0, xr1, wr;

    auto loadX = [&](int it) {
        int off = rX*DD + k0 + it*KSTEP + kq*4;
        xr0 = *(const float4*)(gd.x0 + off);
        xr1 = *(const float4*)(gd.x0 + off + 16);
        if (nx == 3) {
            float4 b = *(const float4*)(gd.x1 + off);
            float4 c = *(const float4*)(gd.x2 + off);
            xr0.x += b.x + c.x; xr0.y += b.y + c.y; xr0.z += b.z + c.z; xr0.w += b.w + c.w;
            b = *(const float4*)(gd.x1 + off + 16);
            c = *(const float4*)(gd.x2 + off + 16);
            xr1.x += b.x + c.x; xr1.y += b.y + c.y; xr1.z += b.z + c.z; xr1.w += b.w + c.w;
        }
    };
    auto loadW = [&](int it) {
        if (!gd.transW) wr = *(const float4*)(gd.w + (size_t)(k0 + it*KSTEP + kwN)*DD + cb + cwN);
        else            wr = *(const float4*)(gd.w + (size_t)(cb + cwT)*DD + k0 + it*KSTEP + kwT);
    };
    auto storeTiles = [&](int b) {
        float* X = sX[b];
        X[(kq*4+0)*66 + rX] = xr0.x;
        X[(kq*4+1)*66 + rX] = xr0.y;
        X[(kq*4+2)*66 + rX] = xr0.z;
        X[(kq*4+3)*66 + rX] = xr0.w;
        X[(16+kq*4+0)*66 + rX] = xr1.x;
        X[(16+kq*4+1)*66 + rX] = xr1.y;
        X[(16+kq*4+2)*66 + rX] = xr1.z;
        X[(16+kq*4+3)*66 + rX] = xr1.w;
        float* W = sW[b];
        if (!gd.transW) {
            *(float2*)&W[kwN*36 + cwN]     = make_float2(wr.x, wr.y);
            *(float2*)&W[kwN*36 + cwN + 2] = make_float2(wr.z, wr.w);
        } else {
            W[(kwT+0)*36 + cwT] = wr.x;
            W[(kwT+1)*36 + cwT] = wr.y;
            W[(kwT+2)*36 + cwT] = wr.z;
            W[(kwT+3)*36 + cwT] = wr.w;
        }
    };

    float a00=0,a01=0,a02=0,a03=0,a10=0,a11=0,a12=0,a13=0;

    loadX(0); loadW(0);
    storeTiles(0);
    __syncthreads();

    for (int it = 0; it < niter; it++) {
        const int b = it & 1;
        if (it + 1 < niter) { loadX(it+1); loadW(it+1); }
        const float* X = sX[b];
        const float* W = sW[b];
#pragma unroll
        for (int k = 0; k < KSTEP; k++) {
            float2 xv = *(const float2*)&X[k*66 + rg*2];
            float4 wv = *(const float4*)&W[k*36 + cg*4];
            a00 += xv.x*wv.x; a01 += xv.x*wv.y; a02 += xv.x*wv.z; a03 += xv.x*wv.w;
            a10 += xv.y*wv.x; a11 += xv.y*wv.y; a12 += xv.y*wv.z; a13 += xv.y*wv.w;
        }
        if (it + 1 < niter) {
            storeTiles(b ^ 1);
            __syncthreads();
        }
    }

    float4 bv = {0.f,0.f,0.f,0.f};
    if (split == 0 && gd.bias) bv = *(const float4*)(gd.bias + cb + cg*4);
    float* y = gd.y + (size_t)split*NB*DD;
    float4 o0 = {a00+bv.x, a01+bv.y, a02+bv.z, a03+bv.w};
    float4 o1 = {a10+bv.x, a11+bv.y, a12+bv.z, a13+bv.w};
    *(float4*)(y + (rg*2+0)*DD + cb + cg*4) = o0;
    *(float4*)(y + (rg*2+1)*DD + cb + cg*4) = o1;
}

// ---------------- attn + prep, 1024 threads, no-max softmax ----------------
__global__ __launch_bounds__(1024) void attn_prep_kernel(const float* __restrict__ module_prob,
                                                         const float* __restrict__ stack_ptr,
                                                         const float* __restrict__ find_kb,
                                                         const float* __restrict__ transform_kb,
                                                         const float* __restrict__ att_stack,
                                                         float* __restrict__ out) {
    int n = blockIdx.x, tid = threadIdx.x;
    int lane = tid & 31, wid = tid >> 5;
    __shared__ float redA[32], redB[32];
    __shared__ float s_pvec[24];

    // bias dots: one j per thread (768 active)
    float s1 = 0.f, s2 = 0.f;
    if (tid < DD) {
        float qv = g_qf[n*DD+tid] + g_qf[NB*DD + n*DD+tid] + g_qf[2*NB*DD + n*DD+tid];
        float tv = g_qt[n*DD+tid] + g_qt[NB*DD + n*DD+tid] + g_qt[2*NB*DD + n*DD+tid];
        s1 = qv*find_kb[tid]; s2 = tv*transform_kb[tid];
    }
#pragma unroll
    for (int o = 16; o; o >>= 1) {
        s1 += __shfl_xor_sync(0xffffffffu, s1, o);
        s2 += __shfl_xor_sync(0xffffffffu, s2, o);
    }
    if (lane == 0) { redA[wid] = s1; redB[wid] = s2; }
    __syncthreads();
    if (tid == 0) {
        float S1 = 0.f, S2 = 0.f;
        for (int w = 0; w < 32; w++) { S1 += redA[w]; S2 += redB[w]; }
        g_biasf[n] = S1*FSCALE; g_biast[n] = S2*FSCALE;

        float ptr[LL], pfw[LL], pb[LL], pbfw[LL], p[MM];
        for (int l = 0; l < LL; l++) ptr[l] = stack_ptr[n*LL + l];
        for (int m = 0; m < MM; m++) p[m] = module_prob[n*MM + m];
        pfw[0] = 0.f;
        for (int l = 1; l < LL; l++) pfw[l] = ptr[l-1];
        pfw[LL-1] += ptr[LL-1];
        for (int l = 0; l < LL-1; l++) pb[l] = ptr[l+1];
        pb[LL-1] = 0.f; pb[0] += ptr[0];
        for (int l = 0; l < LL-1; l++) pbfw[l] = pfw[l+1];
        pbfw[LL-1] = 0.f; pbfw[0] += pfw[0];
        float A = 0.f, Bv = 0.f;
        for (int l = 0; l < LL; l++) { A += pfw[l]*pfw[l]; Bv += pfw[l]*pbfw[l]; }
        g_A[n] = A; g_B[n] = Bv;
        float pav[LL], mx = -1e30f;
        for (int l = 0; l < LL; l++) {
            pav[l] = (p[0]+p[2]+p[7])*ptr[l] + (p[1]+p[6])*pfw[l]
                   + p[3]*pbfw[l] + (p[4]+p[5]+p[8])*pb[l];
            mx = fmaxf(mx, pav[l]*10.0f);
        }
        float sm = 0.f, e[LL];
        for (int l = 0; l < LL; l++) { e[l] = expf(pav[l]*10.0f - mx); sm += e[l]; }
        for (int l = 0; l < LL; l++) out[NB*HWS*LL + n*LL + l] = e[l]/sm;
        for (int l = 0; l < LL; l++) {
            float c0 = p[0]+p[7]+p[8] + (p[1]+p[6])*(1.f-pfw[l]) + p[2]*(1.f-ptr[l])
                     + (p[4]+p[5])*(1.f-pb[l]) + p[3]*(1.f-pfw[l])*(1.f-pbfw[l]);
            g_coef[n*56 + 0*8 + l] = c0;
            g_coef[n*56 + 1*8 + l] = p[1]*pfw[l] + p[3]*pfw[l]*(1.f-pbfw[l]);
            g_coef[n*56 + 2*8 + l] = p[2]*ptr[l];
            g_coef[n*56 + 3*8 + l] = p[3]*pbfw[l];
            g_coef[n*56 + 4*8 + l] = p[4]*pb[l];
            g_coef[n*56 + 5*8 + l] = p[5]*pb[l];
            g_coef[n*56 + 6*8 + l] = p[6]*pfw[l];
            s_pvec[l]      = pb[l];
            s_pvec[8 + l]  = pfw[l]*(1.f-pfw[l]);
            s_pvec[16 + l] = pbfw[l]*(1.f-pfw[l]);
        }
    }
    __syncthreads();

    float pb[LL], h1[LL], h2[LL], pt[LL];
#pragma unroll
    for (int l = 0; l < LL; l++) {
        pb[l] = s_pvec[l];
        h1[l] = s_pvec[8 + l];
        h2[l] = s_pvec[16 + l];
        pt[l] = stack_ptr[n*LL + l];
    }
    const int s = tid;   // one spatial position per thread
    const float* Sr = att_stack + (size_t)n*HWS*LL + s*LL;
    float4 lo = *(const float4*)Sr;
    float4 hi = *(const float4*)(Sr+4);
    float S[8] = {lo.x,lo.y,lo.z,lo.w,hi.x,hi.y,hi.z,hi.w};
    float a1 = 0.f, a2 = 0.f, gg1 = 0.f, gg2 = 0.f;
#pragma unroll
    for (int l = 0; l < 8; l++) {
        a1 += S[l]*pb[l]; a2 += S[l]*pt[l];
        gg1 += S[l]*h1[l]; gg2 += S[l]*h2[l];
    }
    // no-max softmax: |a| is bounded (weights sum<=1, S ~ N(0,1)); exp safe in fp32.
    float w1 = expf(a1), w2 = expf(a2);
    g_att1[n*HWS+s] = a1; g_att2[n*HWS+s] = a2;
    g_g1[n*HWS+s] = gg1;  g_g2[n*HWS+s] = gg2;
    g_w1[n*HWS+s] = w1;   g_w2[n*HWS+s] = w2;

    float t1 = w1, t2 = w2;
#pragma unroll
    for (int o = 16; o; o >>= 1) {
        t1 += __shfl_xor_sync(0xffffffffu, t1, o);
        t2 += __shfl_xor_sync(0xffffffffu, t2, o);
    }
    __syncthreads();   // redA/redB reuse
    if (lane == 0) { redA[wid] = t1; redB[wid] = t2; }
    __syncthreads();
    if (tid == 0) {
        float T1 = 0.f, T2 = 0.f;
        for (int w = 0; w < 32; w++) { T1 += redA[w]; T2 += redB[w]; }
        g_sum1[n] = T1; g_sum2[n] = T2;
    }
}

// ---------------- image pass ----------------
__global__ __launch_bounds__(256) void image_kernel(const float* __restrict__ image_hidden,
                                                    const float* __restrict__ image_mask,
                                                    const float* __restrict__ att_stack,
                                                    const float* __restrict__ scene_w,
                                                    const float* __restrict__ scene_b,
                                                    float* __restrict__ out) {
    int n = blockIdx.y;
    int chunk = blockIdx.x;
    int tid = threadIdx.x, lane = tid & 31, warp = tid >> 5;

    const float4* q0 = (const float4*)(g_qkf + n*DD);
    const float4* q1 = (const float4*)(g_qkf + NB*DD + n*DD);
    const float4* q2 = (const float4*)(g_qkf + 2*NB*DD + n*DD);
    const float4* t0 = (const float4*)(g_qkt + n*DD);
    const float4* t1p = (const float4*)(g_qkt + NB*DD + n*DD);
    const float4* t2p = (const float4*)(g_qkt + 2*NB*DD + n*DD);
    const float4* sw4 = (const float4*)scene_w;

    float4 qkf[6], qkt[6], scw[6], e1[6], e2[6];
#pragma unroll
    for (int j = 0; j < 6; j++) {
        int idx = lane + j*32;
        float4 a = q0[idx], b = q1[idx], c = q2[idx];
        qkf[j] = make_float4(a.x+b.x+c.x, a.y+b.y+c.y, a.z+b.z+c.z, a.w+b.w+c.w);
        a = t0[idx]; b = t1p[idx]; c = t2p[idx];
        qkt[j] = make_float4(a.x+b.x+c.x, a.y+b.y+c.y, a.z+b.z+c.z, a.w+b.w+c.w);
        scw[j] = sw4[idx];
        e1[j] = make_float4(0.f,0.f,0.f,0.f);
        e2[j] = make_float4(0.f,0.f,0.f,0.f);
    }
    float biasf = g_biasf[n], biast = g_biast[n];
    float Av = g_A[n], Bv = g_B[n], scb = scene_b[0];
    float k0=0,k1=0,k2=0,k3=0,k4=0,k5=0,k6=0;
    if (lane < 8) {
        k0 = g_coef[n*56 + lane];      k1 = g_coef[n*56 + 8 + lane];
        k2 = g_coef[n*56 + 16 + lane]; k3 = g_coef[n*56 + 24 + lane];
        k4 = g_coef[n*56 + 32 + lane]; k5 = g_coef[n*56 + 40 + lane];
        k6 = g_coef[n*56 + 48 + lane];
    }

    for (int rp = 0; rp < 8; rp++) {
        int s0 = chunk*128 + warp*16 + rp*2;
        int s1 = s0 + 1;
        const float4* i0 = (const float4*)(image_hidden + ((size_t)n*HWS + s0)*DD) + lane;
        const float4* i1 = (const float4*)(image_hidden + ((size_t)n*HWS + s1)*DD) + lane;
        float4 v0[6], v1[6];
#pragma unroll
        for (int j = 0; j < 6; j++) v0[j] = __ldcs(i0 + j*32);
#pragma unroll
        for (int j = 0; j < 6; j++) v1[j] = __ldcs(i1 + j*32);

        float w1a = g_w1[n*HWS+s0], w2a = g_w2[n*HWS+s0];
        float w1b = g_w1[n*HWS+s1], w2b = g_w2[n*HWS+s1];

        float n2a=0,dfa=0,dta=0,dsa=0,n2b=0,dfb=0,dtb=0,dsb=0;
#pragma unroll
        for (int j = 0; j < 6; j++) {
            float4 a = v0[j], b = v1[j];
            n2a += a.x*a.x + a.y*a.y + a.z*a.z + a.w*a.w;
            n2b += b.x*b.x + b.y*b.y + b.z*b.z + b.w*b.w;
            dfa += a.x*qkf[j].x + a.y*qkf[j].y + a.z*qkf[j].z + a.w*qkf[j].w;
            dfb += b.x*qkf[j].x + b.y*qkf[j].y + b.z*qkf[j].z + b.w*qkf[j].w;
            dta += a.x*qkt[j].x + a.y*qkt[j].y + a.z*qkt[j].z + a.w*qkt[j].w;
            dtb += b.x*qkt[j].x + b.y*qkt[j].y + b.z*qkt[j].z + b.w*qkt[j].w;
            dsa += a.x*scw[j].x + a.y*scw[j].y + a.z*scw[j].z + a.w*scw[j].w;
            dsb += b.x*scw[j].x + b.y*scw[j].y + b.z*scw[j].z + b.w*scw[j].w;
            e1[j].x += w1a*a.x + w1b*b.x; e1[j].y += w1a*a.y + w1b*b.y;
            e1[j].z += w1a*a.z + w1b*b.z; e1[j].w += w1a*a.w + w1b*b.w;
            e2[j].x += w2a*a.x + w2b*b.x; e2[j].y += w2a*a.y + w2b*b.y;
            e2[j].z += w2a*a.z + w2b*b.z; e2[j].w += w2a*a.w + w2b*b.w;
        }
#pragma unroll
        for (int o = 16; o; o >>= 1) {
            n2a += __shfl_xor_sync(0xffffffffu, n2a, o);
            n2b += __shfl_xor_sync(0xffffffffu, n2b, o);
            dfa += __shfl_xor_sync(0xffffffffu, dfa, o);
            dfb += __shfl_xor_sync(0xffffffffu, dfb, o);
            dta += __shfl_xor_sync(0xffffffffu, dta, o);
            dtb += __shfl_xor_sync(0xffffffffu, dtb, o);
            dsa += __shfl_xor_sync(0xffffffffu, dsa, o);
            dsb += __shfl_xor_sync(0xffffffffu, dsb, o);
        }
        {
            float inv = 1.0f / fmaxf(sqrtf(n2a), FEPS);
            float mk = image_mask[n*HWS + s0];
            float sf = dfa*inv*FSCALE + biasf + mk;
            float st = dta*inv*FSCALE + biast + mk;
            float sc = dsa + scb;
            float a1 = g_att1[n*HWS+s0], a2 = g_att2[n*HWS+s0];
            float gg1 = g_g1[n*HWS+s0], gg2 = g_g2[n*HWS+s0];
            float a2f = sf*Av + gg1;
            float a1f = sf*Bv + gg2;
            float mf = fminf(a1f, a2f);
            float mn = fminf(a1, a2);
            float mx = fmaxf(a1, a2);
            if (lane < 8) {
                float Sv = att_stack[((size_t)n*HWS + s0)*LL + lane];
                out[((size_t)n*HWS + s0)*LL + lane] =
                    Sv*k0 + sf*k1 + st*k2 + mf*k3 + mn*k4 + mx*k5 + sc*k6;
            }
        }
        {
            float inv = 1.0f / fmaxf(sqrtf(n2b), FEPS);
            float mk = image_mask[n*HWS + s1];
            float sf = dfb*inv*FSCALE + biasf + mk;
            float st = dtb*inv*FSCALE + biast + mk;
            float sc = dsb + scb;
            float a1 = g_att1[n*HWS+s1], a2 = g_att2[n*HWS+s1];
            float gg1 = g_g1[n*HWS+s1], gg2 = g_g2[n*HWS+s1];
            float a2f = sf*Av + gg1;
            float a1f = sf*Bv + gg2;
            float mf = fminf(a1f, a2f);
            float mn = fminf(a1, a2);
            float mx = fmaxf(a1, a2);
            if (lane < 8) {
                float Sv = att_stack[((size_t)n*HWS + s1)*LL + lane];
                out[((size_t)n*HWS + s1)*LL + lane] =
                    Sv*k0 + sf*k1 + st*k2 + mf*k3 + mn*k4 + mx*k5 + sc*k6;
            }
        }
    }
    __shared__ float extsm[8*1536];
    float4* my1 = (float4*)&extsm[warp*1536];
    float4* my2 = (float4*)&extsm[warp*1536 + 768];
#pragma unroll
    for (int j = 0; j < 6; j++) {
        my1[lane + j*32] = e1[j];
        my2[lane + j*32] = e2[j];
    }
    __syncthreads();
#pragma unroll
    for (int u = 0; u < 6; u++) {
        int idx = tid + u*256;
        float sum = 0.f;
#pragma unroll
        for (int w = 0; w < 8; w++) sum += extsm[w*1536 + idx];
        int e = (idx >= 768) ? 1 : 0;
        int d = idx - e*768;
        g_extpart[((e*NCH) + chunk)*NB*DD + n*DD + d] = sum;
    }
}

// ---------------- reduce extract partials ----------------
__global__ void extreduce_kernel() {
    int n = blockIdx.x, tid = threadIdx.x;
    int d = blockIdx.y*256 + tid;
    float inv1 = 1.0f / g_sum1[n];
    float inv2 = 1.0f / g_sum2[n];
    float e1 = 0.f, e2 = 0.f;
#pragma unroll
    for (int c = 0; c < NCH; c++) {
        e1 += g_extpart[(0*NCH + c)*NB*DD + n*DD + d];
        e2 += g_extpart[(1*NCH + c)*NB*DD + n*DD + d];
    }
    e1 *= inv1; e2 *= inv2;
    float c1v = g_c1[n*DD + d] + g_c1[NB*DD + n*DD + d] + g_c1[2*NB*DD + n*DD + d];
    float c2v = g_c2[n*DD + d] + g_c2[NB*DD + n*DD + d] + g_c2[2*NB*DD + n*DD + d];
    g_e2[n*DD + d]   = e2;
    g_e2c1[n*DD + d] = e2*c1v;
    g_e1c2[n*DD + d] = e1*c2v;
    g_e2c2[n*DD + d] = e2*c2v;
}

// ---------------- final mem combine ----------------
__global__ void memcombine_kernel(const float* __restrict__ module_prob,
                                  const float* __restrict__ mem_prev,
                                  const float* __restrict__ d1b,
                                  const float* __restrict__ d2b,
                                  float* __restrict__ out) {
    int n = blockIdx.x, tid = threadIdx.x;
    int d = blockIdx.y*256 + tid;
    float p0 = module_prob[n*MM + 0];
    float p7 = module_prob[n*MM + 7];
    float p8 = module_prob[n*MM + 8];
    float m1 = g_P[0*NB*DD + n*DD + d] + g_P[1*NB*DD + n*DD + d] + g_P[2*NB*DD + n*DD + d] + d1b[d];
    float m2 = g_P[3*NB*DD + n*DD + d] + g_P[4*NB*DD + n*DD + d] + g_P[5*NB*DD + n*DD + d] + d2b[d];
    out[NB*HWS*LL + NB*LL + n*DD + d] = p0*mem_prev[n*DD + d] + p7*m1 + p8*m2;
}

// ---------------- launch ----------------
extern "C" void kernel_launch(void* const* d_in, const int* in_sizes, int n_in,
                              void* d_out, int out_size) {
    (void)in_sizes; (void)n_in; (void)out_size;
    const float* control   = (const float*)d_in[0];
    const float* mprob     = (const float*)d_in[1];
    const float* mem_prev  = (const float*)d_in[2];
    const float* att_stack = (const float*)d_in[3];
    const float* stack_ptr = (const float*)d_in[4];
    const float* image_h   = (const float*)d_in[8];
    const float* image_m   = (const float*)d_in[9];
    const float* find_ci_w = (const float*)d_in[10];
    const float* find_ci_b = (const float*)d_in[11];
    const float* find_q_w  = (const float*)d_in[12];
    const float* find_q_b  = (const float*)d_in[13];
    const float* find_k_w  = (const float*)d_in[14];
    const float* find_k_b  = (const float*)d_in[15];
    const float* tr_ci_w   = (const float*)d_in[16];
    const float* tr_ci_b   = (const float*)d_in[17];
    const float* tr_q_w    = (const float*)d_in[18];
    const float* tr_q_b    = (const float*)d_in[19];
    const float* tr_k_w    = (const float*)d_in[20];
    const float* tr_k_b    = (const float*)d_in[21];
    const float* scene_w   = (const float*)d_in[22];
    const float* scene_b   = (const float*)d_in[23];
    const float* d1_ci_w   = (const float*)d_in[24];
    const float* d1_ci_b   = (const float*)d_in[25];
    const float* d1_mem_w  = (const float*)d_in[26];
    const float* d1_mem_b  = (const float*)d_in[27];
    const float* d2_ci_w   = (const float*)d_in[28];
    const float* d2_ci_b   = (const float*)d_in[29];
    const float* d2_mem_w  = (const float*)d_in[30];
    const float* d2_mem_b  = (const float*)d_in[31];
    float* out = (float*)d_out;

    float *p_cf, *p_ct, *p_c1, *p_c2, *p_qf, *p_qt, *p_qkf, *p_qkt;
    float *p_e2, *p_e2c1, *p_e1c2, *p_e2c2, *p_P;
    cudaGetSymbolAddress((void**)&p_cf,  g_cf);
    cudaGetSymbolAddress((void**)&p_ct,  g_ct);
    cudaGetSymbolAddress((void**)&p_c1,  g_c1);
    cudaGetSymbolAddress((void**)&p_c2,  g_c2);
    cudaGetSymbolAddress((void**)&p_qf,  g_qf);
    cudaGetSymbolAddress((void**)&p_qt,  g_qt);
    cudaGetSymbolAddress((void**)&p_qkf, g_qkf);
    cudaGetSymbolAddress((void**)&p_qkt, g_qkt);
    cudaGetSymbolAddress((void**)&p_e2,  g_e2);
    cudaGetSymbolAddress((void**)&p_e2c1, g_e2c1);
    cudaGetSymbolAddress((void**)&p_e1c2, g_e1c2);
    cudaGetSymbolAddress((void**)&p_e2c2, g_e2c2);
    cudaGetSymbolAddress((void**)&p_P,   g_P);

    const int ND = NB*DD;

    G2Batch b1 = {};
    b1.nsplit = SPL; b1.nx = 1;
    b1.d[0] = {control, nullptr, nullptr, find_ci_w, find_ci_b, p_cf, 0};
    b1.d[1] = {control, nullptr, nullptr, tr_ci_w,   tr_ci_b,   p_ct, 0};
    b1.d[2] = {control, nullptr, nullptr, d1_ci_w,   d1_ci_b,   p_c1, 0};
    b1.d[3] = {control, nullptr, nullptr, d2_ci_w,   d2_ci_b,   p_c2, 0};
    gemm3_kernel<<<dim3(24,4,SPL), 256>>>(b1);

    G2Batch b2 = {};
    b2.nsplit = SPL; b2.nx = 3;
    b2.d[0] = {p_cf, p_cf+ND, p_cf+2*ND, find_q_w, find_q_b, p_qf, 0};
    b2.d[1] = {p_ct, p_ct+ND, p_ct+2*ND, tr_q_w,   tr_q_b,   p_qt, 0};
    gemm3_kernel<<<dim3(24,2,SPL), 256>>>(b2);

    G2Batch b3 = {};
    b3.nsplit = SPL; b3.nx = 3;
    b3.d[0] = {p_qf, p_qf+ND, p_qf+2*ND, find_k_w, nullptr, p_qkf, 1};
    b3.d[1] = {p_qt, p_qt+ND, p_qt+2*ND, tr_k_w,   nullptr, p_qkt, 1};
    gemm3_kernel<<<dim3(24,2,SPL), 256>>>(b3);

    attn_prep_kernel<<<NB, 1024>>>(mprob, stack_ptr, find_k_b, tr_k_b, att_stack, out);
    image_kernel<<<dim3(NCH, NB), 256>>>(image_h, image_m, att_stack, scene_w, scene_b, out);
    extreduce_kernel<<<dim3(NB,3), 256>>>();

    G2Batch b4 = {};
    b4.nsplit = 1; b4.nx = 1;
    b4.d[0] = {control, nullptr, nullptr, d1_mem_w,             nullptr, p_P + 0*ND, 0};
    b4.d[1] = {p_e2,    nullptr, nullptr, d1_mem_w + DD*DD,     nullptr, p_P + 1*ND, 0};
    b4.d[2] = {p_e2c1,  nullptr, nullptr, d1_mem_w + 2*DD*DD,   nullptr, p_P + 2*ND, 0};
    b4.d[3] = {control, nullptr, nullptr, d2_mem_w,             nullptr, p_P + 3*ND, 0};
    b4.d[4] = {p_e1c2,  nullptr, nullptr, d2_mem_w + DD*DD,     nullptr, p_P + 4*ND, 0};
    b4.d[5] = {p_e2c2,  nullptr, nullptr, d2_mem_w + 2*DD*DD,   nullptr, p_P + 5*ND, 0};
    gemm3_kernel<<<dim3(24,6,1), 256>>>(b4);

    memcombine_kernel<<<dim3(NB,3), 256>>>(mprob, mem_prev, d1_mem_b, d2_mem_b, out);
}

// round 5
// speedup vs baseline: 2.4223x; 1.5043x over previous
#include <cuda_runtime.h>
#include <math.h>

#define NB 64
#define DD 768
#define HWS 1024
#define LL 8
#define MM 9
#define NCH 8
#define SPL 3
#define KSTEP 32
#define FSCALE 0.03608439182435161f
#define FEPS 1e-12f

// ---------------- scratch ----------------
__device__ float g_cf[SPL*NB*DD], g_ct[SPL*NB*DD], g_c1[SPL*NB*DD], g_c2[SPL*NB*DD];
__device__ float g_qf[SPL*NB*DD], g_qt[SPL*NB*DD], g_qkf[SPL*NB*DD], g_qkt[SPL*NB*DD];
__device__ float g_biasf[NB], g_biast[NB], g_A[NB], g_B[NB];
__device__ float g_coef[NB*56];
__device__ float g_att1[NB*HWS], g_att2[NB*HWS];
__device__ float g_w1[NB*HWS], g_w2[NB*HWS];
__device__ float g_g1[NB*HWS], g_g2[NB*HWS];
__device__ float g_sum1[NB], g_sum2[NB];
__device__ float g_extpart[2*NCH*NB*DD];
__device__ float g_e2[NB*DD], g_e2c1[NB*DD], g_e1c2[NB*DD], g_e2c2[NB*DD];
__device__ float g_P[6*NB*DD];

// ---------------- GEMM v3: double-buffered, KSTEP=32 ----------------
struct G2Desc { const float* x0; const float* x1; const float* x2;
                const float* w; const float* bias; float* y; int transW; };
struct G2Batch { G2Desc d[6]; int nsplit; int nx; };

__global__ __launch_bounds__(256) void gemm3_kernel(G2Batch batch) {
    G2Desc gd = batch.d[blockIdx.y];
    const int split = blockIdx.z;
    const int klen = DD / batch.nsplit;
    const int k0 = split * klen;
    const int cb = blockIdx.x * 32;
    const int nx = batch.nx;
    const int niter = klen / KSTEP;

    __shared__ float sX[2][KSTEP*66];
    __shared__ float sW[2][KSTEP*36];

    const int tid = threadIdx.x;
    const int rg = tid >> 3;
    const int cg = tid & 7;
    const int rX = tid >> 2;
    const int kq = tid & 3;
    const int kwN = tid >> 3;
    const int cwN = (tid & 7) * 4;
    const int cwT = tid >> 3;
    const int kwT = (tid & 7) * 4;

    float4 xr0, xr1, wr;

    auto loadX = [&](int it) {
        int off = rX*DD + k0 + it*KSTEP + kq*4;
        xr0 = *(const float4*)(gd.x0 + off);
        xr1 = *(const float4*)(gd.x0 + off + 16);
        if (nx == 3) {
            float4 b = *(const float4*)(gd.x1 + off);
            float4 c = *(const float4*)(gd.x2 + off);
            xr0.x += b.x + c.x; xr0.y += b.y + c.y; xr0.z += b.z + c.z; xr0.w += b.w + c.w;
            b = *(const float4*)(gd.x1 + off + 16);
            c = *(const float4*)(gd.x2 + off + 16);
            xr1.x += b.x + c.x; xr1.y += b.y + c.y; xr1.z += b.z + c.z; xr1.w += b.w + c.w;
        }
    };
    auto loadW = [&](int it) {
        if (!gd.transW) wr = *(const float4*)(gd.w + (size_t)(k0 + it*KSTEP + kwN)*DD + cb + cwN);
        else            wr = *(const float4*)(gd.w + (size_t)(cb + cwT)*DD + k0 + it*KSTEP + kwT);
    };
    auto storeTiles = [&](int b) {
        float* X = sX[b];
        X[(kq*4+0)*66 + rX] = xr0.x;
        X[(kq*4+1)*66 + rX] = xr0.y;
        X[(kq*4+2)*66 + rX] = xr0.z;
        X[(kq*4+3)*66 + rX] = xr0.w;
        X[(16+kq*4+0)*66 + rX] = xr1.x;
        X[(16+kq*4+1)*66 + rX] = xr1.y;
        X[(16+kq*4+2)*66 + rX] = xr1.z;
        X[(16+kq*4+3)*66 + rX] = xr1.w;
        float* W = sW[b];
        if (!gd.transW) {
            *(float2*)&W[kwN*36 + cwN]     = make_float2(wr.x, wr.y);
            *(float2*)&W[kwN*36 + cwN + 2] = make_float2(wr.z, wr.w);
        } else {
            W[(kwT+0)*36 + cwT] = wr.x;
            W[(kwT+1)*36 + cwT] = wr.y;
            W[(kwT+2)*36 + cwT] = wr.z;
            W[(kwT+3)*36 + cwT] = wr.w;
        }
    };

    float a00=0,a01=0,a02=0,a03=0,a10=0,a11=0,a12=0,a13=0;

    loadX(0); loadW(0);
    storeTiles(0);
    __syncthreads();

    for (int it = 0; it < niter; it++) {
        const int b = it & 1;
        if (it + 1 < niter) { loadX(it+1); loadW(it+1); }
        const float* X = sX[b];
        const float* W = sW[b];
#pragma unroll
        for (int k = 0; k < KSTEP; k++) {
            float2 xv = *(const float2*)&X[k*66 + rg*2];
            float4 wv = *(const float4*)&W[k*36 + cg*4];
            a00 += xv.x*wv.x; a01 += xv.x*wv.y; a02 += xv.x*wv.z; a03 += xv.x*wv.w;
            a10 += xv.y*wv.x; a11 += xv.y*wv.y; a12 += xv.y*wv.z; a13 += xv.y*wv.w;
        }
        if (it + 1 < niter) {
            storeTiles(b ^ 1);
            __syncthreads();
        }
    }

    float4 bv = {0.f,0.f,0.f,0.f};
    if (split == 0 && gd.bias) bv = *(const float4*)(gd.bias + cb + cg*4);
    float* y = gd.y + (size_t)split*NB*DD;
    float4 o0 = {a00+bv.x, a01+bv.y, a02+bv.z, a03+bv.w};
    float4 o1 = {a10+bv.x, a11+bv.y, a12+bv.z, a13+bv.w};
    *(float4*)(y + (rg*2+0)*DD + cb + cg*4) = o0;
    *(float4*)(y + (rg*2+1)*DD + cb + cg*4) = o1;
}

// ---------------- attn + prep ----------------
__global__ __launch_bounds__(1024) void attn_prep_kernel(const float* __restrict__ module_prob,
                                                         const float* __restrict__ stack_ptr,
                                                         const float* __restrict__ find_kb,
                                                         const float* __restrict__ transform_kb,
                                                         const float* __restrict__ att_stack,
                                                         float* __restrict__ out) {
    int n = blockIdx.x, tid = threadIdx.x;
    int lane = tid & 31, wid = tid >> 5;
    __shared__ float redA[32], redB[32];
    __shared__ float s_pvec[24];

    float s1 = 0.f, s2 = 0.f;
    if (tid < DD) {
        float qv = g_qf[n*DD+tid] + g_qf[NB*DD + n*DD+tid] + g_qf[2*NB*DD + n*DD+tid];
        float tv = g_qt[n*DD+tid] + g_qt[NB*DD + n*DD+tid] + g_qt[2*NB*DD + n*DD+tid];
        s1 = qv*find_kb[tid]; s2 = tv*transform_kb[tid];
    }
#pragma unroll
    for (int o = 16; o; o >>= 1) {
        s1 += __shfl_xor_sync(0xffffffffu, s1, o);
        s2 += __shfl_xor_sync(0xffffffffu, s2, o);
    }
    if (lane == 0) { redA[wid] = s1; redB[wid] = s2; }
    __syncthreads();
    if (tid == 0) {
        float S1 = 0.f, S2 = 0.f;
        for (int w = 0; w < 32; w++) { S1 += redA[w]; S2 += redB[w]; }
        g_biasf[n] = S1*FSCALE; g_biast[n] = S2*FSCALE;

        float ptr[LL], pfw[LL], pb[LL], pbfw[LL], p[MM];
        for (int l = 0; l < LL; l++) ptr[l] = stack_ptr[n*LL + l];
        for (int m = 0; m < MM; m++) p[m] = module_prob[n*MM + m];
        pfw[0] = 0.f;
        for (int l = 1; l < LL; l++) pfw[l] = ptr[l-1];
        pfw[LL-1] += ptr[LL-1];
        for (int l = 0; l < LL-1; l++) pb[l] = ptr[l+1];
        pb[LL-1] = 0.f; pb[0] += ptr[0];
        for (int l = 0; l < LL-1; l++) pbfw[l] = pfw[l+1];
        pbfw[LL-1] = 0.f; pbfw[0] += pfw[0];
        float A = 0.f, Bv = 0.f;
        for (int l = 0; l < LL; l++) { A += pfw[l]*pfw[l]; Bv += pfw[l]*pbfw[l]; }
        g_A[n] = A; g_B[n] = Bv;
        float pav[LL], mx = -1e30f;
        for (int l = 0; l < LL; l++) {
            pav[l] = (p[0]+p[2]+p[7])*ptr[l] + (p[1]+p[6])*pfw[l]
                   + p[3]*pbfw[l] + (p[4]+p[5]+p[8])*pb[l];
            mx = fmaxf(mx, pav[l]*10.0f);
        }
        float sm = 0.f, e[LL];
        for (int l = 0; l < LL; l++) { e[l] = expf(pav[l]*10.0f - mx); sm += e[l]; }
        for (int l = 0; l < LL; l++) out[NB*HWS*LL + n*LL + l] = e[l]/sm;
        for (int l = 0; l < LL; l++) {
            float c0 = p[0]+p[7]+p[8] + (p[1]+p[6])*(1.f-pfw[l]) + p[2]*(1.f-ptr[l])
                     + (p[4]+p[5])*(1.f-pb[l]) + p[3]*(1.f-pfw[l])*(1.f-pbfw[l]);
            g_coef[n*56 + 0*8 + l] = c0;
            g_coef[n*56 + 1*8 + l] = p[1]*pfw[l] + p[3]*pfw[l]*(1.f-pbfw[l]);
            g_coef[n*56 + 2*8 + l] = p[2]*ptr[l];
            g_coef[n*56 + 3*8 + l] = p[3]*pbfw[l];
            g_coef[n*56 + 4*8 + l] = p[4]*pb[l];
            g_coef[n*56 + 5*8 + l] = p[5]*pb[l];
            g_coef[n*56 + 6*8 + l] = p[6]*pfw[l];
            s_pvec[l]      = pb[l];
            s_pvec[8 + l]  = pfw[l]*(1.f-pfw[l]);
            s_pvec[16 + l] = pbfw[l]*(1.f-pfw[l]);
        }
    }
    __syncthreads();

    float pb[LL], h1[LL], h2[LL], pt[LL];
#pragma unroll
    for (int l = 0; l < LL; l++) {
        pb[l] = s_pvec[l];
        h1[l] = s_pvec[8 + l];
        h2[l] = s_pvec[16 + l];
        pt[l] = stack_ptr[n*LL + l];
    }
    const int s = tid;
    const float* Sr = att_stack + (size_t)n*HWS*LL + s*LL;
    float4 lo = *(const float4*)Sr;
    float4 hi = *(const float4*)(Sr+4);
    float S[8] = {lo.x,lo.y,lo.z,lo.w,hi.x,hi.y,hi.z,hi.w};
    float a1 = 0.f, a2 = 0.f, gg1 = 0.f, gg2 = 0.f;
#pragma unroll
    for (int l = 0; l < 8; l++) {
        a1 += S[l]*pb[l]; a2 += S[l]*pt[l];
        gg1 += S[l]*h1[l]; gg2 += S[l]*h2[l];
    }
    float w1 = expf(a1), w2 = expf(a2);
    g_att1[n*HWS+s] = a1; g_att2[n*HWS+s] = a2;
    g_g1[n*HWS+s] = gg1;  g_g2[n*HWS+s] = gg2;
    g_w1[n*HWS+s] = w1;   g_w2[n*HWS+s] = w2;

    float t1 = w1, t2 = w2;
#pragma unroll
    for (int o = 16; o; o >>= 1) {
        t1 += __shfl_xor_sync(0xffffffffu, t1, o);
        t2 += __shfl_xor_sync(0xffffffffu, t2, o);
    }
    __syncthreads();
    if (lane == 0) { redA[wid] = t1; redB[wid] = t2; }
    __syncthreads();
    if (tid == 0) {
        float T1 = 0.f, T2 = 0.f;
        for (int w = 0; w < 32; w++) { T1 += redA[w]; T2 += redB[w]; }
        g_sum1[n] = T1; g_sum2[n] = T2;
    }
}

// ---------------- image pass v2: warp = (32-row group) x (384-col half) ----------------
__global__ __launch_bounds__(256) void image_kernel(const float* __restrict__ image_hidden,
                                                    const float* __restrict__ image_mask,
                                                    const float* __restrict__ att_stack,
                                                    const float* __restrict__ scene_w,
                                                    const float* __restrict__ scene_b,
                                                    float* __restrict__ out) {
    const int n = blockIdx.y;
    const int chunk = blockIdx.x;
    const int tid = threadIdx.x, lane = tid & 31, w = tid >> 5;
    const int h = w & 1;          // D-half: cols [h*384, h*384+384)
    const int g = w >> 1;         // row group: 32 rows

    __shared__ float eps1[4][768];
    __shared__ float eps2[4][768];
    __shared__ float sdots[128][8];   // [row][h*4 + {n2,df,dt,dsc}]

    const float4* q0 = (const float4*)(g_qkf + n*DD);
    const float4* q1 = (const float4*)(g_qkf + NB*DD + n*DD);
    const float4* q2 = (const float4*)(g_qkf + 2*NB*DD + n*DD);
    const float4* t0 = (const float4*)(g_qkt + n*DD);
    const float4* t1p = (const float4*)(g_qkt + NB*DD + n*DD);
    const float4* t2p = (const float4*)(g_qkt + 2*NB*DD + n*DD);
    const float4* sw4 = (const float4*)scene_w;

    const int base4 = h*96 + lane;    // float4 index into 192-wide row
    float4 qkf[3], qkt[3], scw[3], e1[3], e2[3];
#pragma unroll
    for (int j = 0; j < 3; j++) {
        int idx = base4 + j*32;
        float4 a = q0[idx], b = q1[idx], c = q2[idx];
        qkf[j] = make_float4(a.x+b.x+c.x, a.y+b.y+c.y, a.z+b.z+c.z, a.w+b.w+c.w);
        a = t0[idx]; b = t1p[idx]; c = t2p[idx];
        qkt[j] = make_float4(a.x+b.x+c.x, a.y+b.y+c.y, a.z+b.z+c.z, a.w+b.w+c.w);
        scw[j] = sw4[idx];
        e1[j] = make_float4(0.f,0.f,0.f,0.f);
        e2[j] = make_float4(0.f,0.f,0.f,0.f);
    }

    const int row0 = chunk*128 + g*32;
    for (int rp = 0; rp < 16; rp++) {
        const int s0 = row0 + rp*2;
        const int s1 = s0 + 1;
        const float4* i0 = (const float4*)(image_hidden + ((size_t)n*HWS + s0)*DD) + base4;
        const float4* i1 = (const float4*)(image_hidden + ((size_t)n*HWS + s1)*DD) + base4;
        float4 v0[3], v1[3];
#pragma unroll
        for (int j = 0; j < 3; j++) v0[j] = __ldcs(i0 + j*32);
#pragma unroll
        for (int j = 0; j < 3; j++) v1[j] = __ldcs(i1 + j*32);

        float w1a = g_w1[n*HWS+s0], w2a = g_w2[n*HWS+s0];
        float w1b = g_w1[n*HWS+s1], w2b = g_w2[n*HWS+s1];

        float n2a=0,dfa=0,dta=0,dsa=0,n2b=0,dfb=0,dtb=0,dsb=0;
#pragma unroll
        for (int j = 0; j < 3; j++) {
            float4 a = v0[j], b = v1[j];
            n2a += a.x*a.x + a.y*a.y + a.z*a.z + a.w*a.w;
            n2b += b.x*b.x + b.y*b.y + b.z*b.z + b.w*b.w;
            dfa += a.x*qkf[j].x + a.y*qkf[j].y + a.z*qkf[j].z + a.w*qkf[j].w;
            dfb += b.x*qkf[j].x + b.y*qkf[j].y + b.z*qkf[j].z + b.w*qkf[j].w;
            dta += a.x*qkt[j].x + a.y*qkt[j].y + a.z*qkt[j].z + a.w*qkt[j].w;
            dtb += b.x*qkt[j].x + b.y*qkt[j].y + b.z*qkt[j].z + b.w*qkt[j].w;
            dsa += a.x*scw[j].x + a.y*scw[j].y + a.z*scw[j].z + a.w*scw[j].w;
            dsb += b.x*scw[j].x + b.y*scw[j].y + b.z*scw[j].z + b.w*scw[j].w;
            e1[j].x += w1a*a.x + w1b*b.x; e1[j].y += w1a*a.y + w1b*b.y;
            e1[j].z += w1a*a.z + w1b*b.z; e1[j].w += w1a*a.w + w1b*b.w;
            e2[j].x += w2a*a.x + w2b*b.x; e2[j].y += w2a*a.y + w2b*b.y;
            e2[j].z += w2a*a.z + w2b*b.z; e2[j].w += w2a*a.w + w2b*b.w;
        }
#pragma unroll
        for (int o = 16; o; o >>= 1) {
            n2a += __shfl_xor_sync(0xffffffffu, n2a, o);
            n2b += __shfl_xor_sync(0xffffffffu, n2b, o);
            dfa += __shfl_xor_sync(0xffffffffu, dfa, o);
            dfb += __shfl_xor_sync(0xffffffffu, dfb, o);
            dta += __shfl_xor_sync(0xffffffffu, dta, o);
            dtb += __shfl_xor_sync(0xffffffffu, dtb, o);
            dsa += __shfl_xor_sync(0xffffffffu, dsa, o);
            dsb += __shfl_xor_sync(0xffffffffu, dsb, o);
        }
        if (lane == 0) {
            int r0 = g*32 + rp*2;
            sdots[r0][h*4+0] = n2a; sdots[r0][h*4+1] = dfa;
            sdots[r0][h*4+2] = dta; sdots[r0][h*4+3] = dsa;
            sdots[r0+1][h*4+0] = n2b; sdots[r0+1][h*4+1] = dfb;
            sdots[r0+1][h*4+2] = dtb; sdots[r0+1][h*4+3] = dsb;
        }
    }
    // stash e-partials
    {
        float4* d1 = (float4*)&eps1[g][h*384];
        float4* d2 = (float4*)&eps2[g][h*384];
#pragma unroll
        for (int j = 0; j < 3; j++) {
            d1[lane + j*32] = e1[j];
            d2[lane + j*32] = e2[j];
        }
    }
    __syncthreads();

    // final e-reduce across 4 row groups -> g_extpart
#pragma unroll
    for (int u = 0; u < 6; u++) {
        int idx = tid + u*256;            // 0..1535
        int e = (idx >= 768) ? 1 : 0;
        int d = idx - e*768;
        float sum;
        if (e == 0) sum = eps1[0][d] + eps1[1][d] + eps1[2][d] + eps1[3][d];
        else        sum = eps2[0][d] + eps2[1][d] + eps2[2][d] + eps2[3][d];
        g_extpart[((e*NCH) + chunk)*NB*DD + n*DD + d] = sum;
    }

    // score phase: 2 threads per row
    {
        const int r = tid >> 1;
        const int sub = tid & 1;
        const int s = chunk*128 + r;
        float n2 = sdots[r][0] + sdots[r][4];
        float df = sdots[r][1] + sdots[r][5];
        float dt = sdots[r][2] + sdots[r][6];
        float dsc = sdots[r][3] + sdots[r][7];
        float biasf = g_biasf[n], biast = g_biast[n];
        float Av = g_A[n], Bv = g_B[n], scb = scene_b[0];
        float inv = 1.0f / fmaxf(sqrtf(n2), FEPS);
        float mk = image_mask[n*HWS + s];
        float sf = df*inv*FSCALE + biasf + mk;
        float st = dt*inv*FSCALE + biast + mk;
        float sc = dsc + scb;
        float a1 = g_att1[n*HWS+s], a2 = g_att2[n*HWS+s];
        float gg1 = g_g1[n*HWS+s], gg2 = g_g2[n*HWS+s];
        float a2f = sf*Av + gg1;
        float a1f = sf*Bv + gg2;
        float mf = fminf(a1f, a2f);
        float mn = fminf(a1, a2);
        float mx = fmaxf(a1, a2);
        const float* cf = g_coef + n*56 + sub*4;
        float4 K0 = *(const float4*)(cf + 0);
        float4 K1 = *(const float4*)(cf + 8);
        float4 K2 = *(const float4*)(cf + 16);
        float4 K3 = *(const float4*)(cf + 24);
        float4 K4 = *(const float4*)(cf + 32);
        float4 K5 = *(const float4*)(cf + 40);
        float4 K6 = *(const float4*)(cf + 48);
        float4 Sv = *(const float4*)(att_stack + ((size_t)n*HWS + s)*LL + sub*4);
        float4 o;
        o.x = Sv.x*K0.x + sf*K1.x + st*K2.x + mf*K3.x + mn*K4.x + mx*K5.x + sc*K6.x;
        o.y = Sv.y*K0.y + sf*K1.y + st*K2.y + mf*K3.y + mn*K4.y + mx*K5.y + sc*K6.y;
        o.z = Sv.z*K0.z + sf*K1.z + st*K2.z + mf*K3.z + mn*K4.z + mx*K5.z + sc*K6.z;
        o.w = Sv.w*K0.w + sf*K1.w + st*K2.w + mf*K3.w + mn*K4.w + mx*K5.w + sc*K6.w;
        *(float4*)(out + ((size_t)n*HWS + s)*LL + sub*4) = o;
    }
}

// ---------------- reduce extract partials ----------------
__global__ void extreduce_kernel() {
    int n = blockIdx.x, tid = threadIdx.x;
    int d = blockIdx.y*256 + tid;
    float inv1 = 1.0f / g_sum1[n];
    float inv2 = 1.0f / g_sum2[n];
    float e1 = 0.f, e2 = 0.f;
#pragma unroll
    for (int c = 0; c < NCH; c++) {
        e1 += g_extpart[(0*NCH + c)*NB*DD + n*DD + d];
        e2 += g_extpart[(1*NCH + c)*NB*DD + n*DD + d];
    }
    e1 *= inv1; e2 *= inv2;
    float c1v = g_c1[n*DD + d] + g_c1[NB*DD + n*DD + d] + g_c1[2*NB*DD + n*DD + d];
    float c2v = g_c2[n*DD + d] + g_c2[NB*DD + n*DD + d] + g_c2[2*NB*DD + n*DD + d];
    g_e2[n*DD + d]   = e2;
    g_e2c1[n*DD + d] = e2*c1v;
    g_e1c2[n*DD + d] = e1*c2v;
    g_e2c2[n*DD + d] = e2*c2v;
}

// ---------------- final mem combine ----------------
__global__ void memcombine_kernel(const float* __restrict__ module_prob,
                                  const float* __restrict__ mem_prev,
                                  const float* __restrict__ d1b,
                                  const float* __restrict__ d2b,
                                  float* __restrict__ out) {
    int n = blockIdx.x, tid = threadIdx.x;
    int d = blockIdx.y*256 + tid;
    float p0 = module_prob[n*MM + 0];
    float p7 = module_prob[n*MM + 7];
    float p8 = module_prob[n*MM + 8];
    float m1 = g_P[0*NB*DD + n*DD + d] + g_P[1*NB*DD + n*DD + d] + g_P[2*NB*DD + n*DD + d] + d1b[d];
    float m2 = g_P[3*NB*DD + n*DD + d] + g_P[4*NB*DD + n*DD + d] + g_P[5*NB*DD + n*DD + d] + d2b[d];
    out[NB*HWS*LL + NB*LL + n*DD + d] = p0*mem_prev[n*DD + d] + p7*m1 + p8*m2;
}

// ---------------- launch ----------------
extern "C" void kernel_launch(void* const* d_in, const int* in_sizes, int n_in,
                              void* d_out, int out_size) {
    (void)in_sizes; (void)n_in; (void)out_size;
    const float* control   = (const float*)d_in[0];
    const float* mprob     = (const float*)d_in[1];
    const float* mem_prev  = (const float*)d_in[2];
    const float* att_stack = (const float*)d_in[3];
    const float* stack_ptr = (const float*)d_in[4];
    const float* image_h   = (const float*)d_in[8];
    const float* image_m   = (const float*)d_in[9];
    const float* find_ci_w = (const float*)d_in[10];
    const float* find_ci_b = (const float*)d_in[11];
    const float* find_q_w  = (const float*)d_in[12];
    const float* find_q_b  = (const float*)d_in[13];
    const float* find_k_w  = (const float*)d_in[14];
    const float* find_k_b  = (const float*)d_in[15];
    const float* tr_ci_w   = (const float*)d_in[16];
    const float* tr_ci_b   = (const float*)d_in[17];
    const float* tr_q_w    = (const float*)d_in[18];
    const float* tr_q_b    = (const float*)d_in[19];
    const float* tr_k_w    = (const float*)d_in[20];
    const float* tr_k_b    = (const float*)d_in[21];
    const float* scene_w   = (const float*)d_in[22];
    const float* scene_b   = (const float*)d_in[23];
    const float* d1_ci_w   = (const float*)d_in[24];
    const float* d1_ci_b   = (const float*)d_in[25];
    const float* d1_mem_w  = (const float*)d_in[26];
    const float* d1_mem_b  = (const float*)d_in[27];
    const float* d2_ci_w   = (const float*)d_in[28];
    const float* d2_ci_b   = (const float*)d_in[29];
    const float* d2_mem_w  = (const float*)d_in[30];
    const float* d2_mem_b  = (const float*)d_in[31];
    float* out = (float*)d_out;

    float *p_cf, *p_ct, *p_c1, *p_c2, *p_qf, *p_qt, *p_qkf, *p_qkt;
    float *p_e2, *p_e2c1, *p_e1c2, *p_e2c2, *p_P;
    cudaGetSymbolAddress((void**)&p_cf,  g_cf);
    cudaGetSymbolAddress((void**)&p_ct,  g_ct);
    cudaGetSymbolAddress((void**)&p_c1,  g_c1);
    cudaGetSymbolAddress((void**)&p_c2,  g_c2);
    cudaGetSymbolAddress((void**)&p_qf,  g_qf);
    cudaGetSymbolAddress((void**)&p_qt,  g_qt);
    cudaGetSymbolAddress((void**)&p_qkf, g_qkf);
    cudaGetSymbolAddress((void**)&p_qkt, g_qkt);
    cudaGetSymbolAddress((void**)&p_e2,  g_e2);
    cudaGetSymbolAddress((void**)&p_e2c1, g_e2c1);
    cudaGetSymbolAddress((void**)&p_e1c2, g_e1c2);
    cudaGetSymbolAddress((void**)&p_e2c2, g_e2c2);
    cudaGetSymbolAddress((void**)&p_P,   g_P);

    const int ND = NB*DD;

    G2Batch b1 = {};
    b1.nsplit = SPL; b1.nx = 1;
    b1.d[0] = {control, nullptr, nullptr, find_ci_w, find_ci_b, p_cf, 0};
    b1.d[1] = {control, nullptr, nullptr, tr_ci_w,   tr_ci_b,   p_ct, 0};
    b1.d[2] = {control, nullptr, nullptr, d1_ci_w,   d1_ci_b,   p_c1, 0};
    b1.d[3] = {control, nullptr, nullptr, d2_ci_w,   d2_ci_b,   p_c2, 0};
    gemm3_kernel<<<dim3(24,4,SPL), 256>>>(b1);

    G2Batch b2 = {};
    b2.nsplit = SPL; b2.nx = 3;
    b2.d[0] = {p_cf, p_cf+ND, p_cf+2*ND, find_q_w, find_q_b, p_qf, 0};
    b2.d[1] = {p_ct, p_ct+ND, p_ct+2*ND, tr_q_w,   tr_q_b,   p_qt, 0};
    gemm3_kernel<<<dim3(24,2,SPL), 256>>>(b2);

    G2Batch b3 = {};
    b3.nsplit = SPL; b3.nx = 3;
    b3.d[0] = {p_qf, p_qf+ND, p_qf+2*ND, find_k_w, nullptr, p_qkf, 1};
    b3.d[1] = {p_qt, p_qt+ND, p_qt+2*ND, tr_k_w,   nullptr, p_qkt, 1};
    gemm3_kernel<<<dim3(24,2,SPL), 256>>>(b3);

    attn_prep_kernel<<<NB, 1024>>>(mprob, stack_ptr, find_k_b, tr_k_b, att_stack, out);
    image_kernel<<<dim3(NCH, NB), 256>>>(image_h, image_m, att_stack, scene_w, scene_b, out);
    extreduce_kernel<<<dim3(NB,3), 256>>>();

    G2Batch b4 = {};
    b4.nsplit = 1; b4.nx = 1;
    b4.d[0] = {control, nullptr, nullptr, d1_mem_w,             nullptr, p_P + 0*ND, 0};
    b4.d[1] = {p_e2,    nullptr, nullptr, d1_mem_w + DD*DD,     nullptr, p_P + 1*ND, 0};
    b4.d[2] = {p_e2c1,  nullptr, nullptr, d1_mem_w + 2*DD*DD,   nullptr, p_P + 2*ND, 0};
    b4.d[3] = {control, nullptr, nullptr, d2_mem_w,             nullptr, p_P + 3*ND, 0};
    b4.d[4] = {p_e1c2,  nullptr, nullptr, d2_mem_w + DD*DD,     nullptr, p_P + 4*ND, 0};
    b4.d[5] = {p_e2c2,  nullptr, nullptr, d2_mem_w + 2*DD*DD,   nullptr, p_P + 5*ND, 0};
    gemm3_kernel<<<dim3(24,6,1), 256>>>(b4);

    memcombine_kernel<<<dim3(NB,3), 256>>>(mprob, mem_prev, d1_mem_b, d2_mem_b, out);
}

// round 8
// speedup vs baseline: 2.6092x; 1.0771x over previous
#include <cuda_runtime.h>
#include <math.h>

#define NB 64
#define DD 768
#define HWS 1024
#define LL 8
#define MM 9
#define NCH 8
#define SPL 3
#define KSTEP 32
#define ND (NB*DD)
#define FSCALE 0.03608439182435161f
#define FEPS 1e-12f

// ---------------- scratch ----------------
__device__ float g_cf[SPL*NB*DD], g_ct[SPL*NB*DD], g_c1[SPL*NB*DD], g_c2[SPL*NB*DD];
__device__ float g_qf[SPL*NB*DD], g_qt[SPL*NB*DD], g_qkf[SPL*NB*DD], g_qkt[SPL*NB*DD];
__device__ float g_biasf[NB], g_biast[NB], g_A[NB], g_B[NB];
__device__ float g_coef[NB*56];
__device__ float g_pvec[NB*32];     // pb[8], h1[8], h2[8], pt[8]
__device__ float g_wsum1[NB*NCH], g_wsum2[NB*NCH];
__device__ float g_extpart[2*NCH*NB*DD];
__device__ float g_e2[NB*DD], g_e2c1[NB*DD], g_e1c2[NB*DD], g_e2c2[NB*DD];
__device__ float g_P[6*NB*DD];
__device__ int   g_cnt[NB];
__device__ int   g_cnt2[24];

// ---------------- GEMM v3: double-buffered, KSTEP=32, optional fused mem-combine ----------------
struct G2Desc { const float* x0; const float* x1; const float* x2;
                const float* w; const float* bias; float* y; int transW; };
struct G2Batch { G2Desc d[6]; int nsplit; int nx; int docombine;
                 const float* mprob; const float* memprev;
                 const float* d1b; const float* d2b; float* outp; };

__global__ __launch_bounds__(256) void gemm3_kernel(G2Batch batch) {
    G2Desc gd = batch.d[blockIdx.y];
    const int split = blockIdx.z;
    const int klen = DD / batch.nsplit;
    const int k0 = split * klen;
    const int cb = blockIdx.x * 32;
    const int nx = batch.nx;
    const int niter = klen / KSTEP;

    __shared__ float sX[2][KSTEP*66];
    __shared__ float sW[2][KSTEP*36];

    const int tid = threadIdx.x;
    const int rg = tid >> 3;
    const int cg = tid & 7;
    const int rX = tid >> 2;
    const int kq = tid & 3;
    const int kwN = tid >> 3;
    const int cwN = (tid & 7) * 4;
    const int cwT = tid >> 3;
    const int kwT = (tid & 7) * 4;

    float4 xr0, xr1, wr;

    auto loadX = [&](int it) {
        int off = rX*DD + k0 + it*KSTEP + kq*4;
        xr0 = *(const float4*)(gd.x0 + off);
        xr1 = *(const float4*)(gd.x0 + off + 16);
        if (nx == 3) {
            float4 b = *(const float4*)(gd.x1 + off);
            float4 c = *(const float4*)(gd.x2 + off);
            xr0.x += b.x + c.x; xr0.y += b.y + c.y; xr0.z += b.z + c.z; xr0.w += b.w + c.w;
            b = *(const float4*)(gd.x1 + off + 16);
            c = *(const float4*)(gd.x2 + off + 16);
            xr1.x += b.x + c.x; xr1.y += b.y + c.y; xr1.z += b.z + c.z; xr1.w += b.w + c.w;
        }
    };
    auto loadW = [&](int it) {
        if (!gd.transW) wr = *(const float4*)(gd.w + (size_t)(k0 + it*KSTEP + kwN)*DD + cb + cwN);
        else            wr = *(const float4*)(gd.w + (size_t)(cb + cwT)*DD + k0 + it*KSTEP + kwT);
    };
    auto storeTiles = [&](int b) {
        float* X = sX[b];
        X[(kq*4+0)*66 + rX] = xr0.x;
        X[(kq*4+1)*66 + rX] = xr0.y;
        X[(kq*4+2)*66 + rX] = xr0.z;
        X[(kq*4+3)*66 + rX] = xr0.w;
        X[(16+kq*4+0)*66 + rX] = xr1.x;
        X[(16+kq*4+1)*66 + rX] = xr1.y;
        X[(16+kq*4+2)*66 + rX] = xr1.z;
        X[(16+kq*4+3)*66 + rX] = xr1.w;
        float* W = sW[b];
        if (!gd.transW) {
            *(float2*)&W[kwN*36 + cwN]     = make_float2(wr.x, wr.y);
            *(float2*)&W[kwN*36 + cwN + 2] = make_float2(wr.z, wr.w);
        } else {
            W[(kwT+0)*36 + cwT] = wr.x;
            W[(kwT+1)*36 + cwT] = wr.y;
            W[(kwT+2)*36 + cwT] = wr.z;
            W[(kwT+3)*36 + cwT] = wr.w;
        }
    };

    float a00=0,a01=0,a02=0,a03=0,a10=0,a11=0,a12=0,a13=0;

    loadX(0); loadW(0);
    storeTiles(0);
    __syncthreads();

    for (int it = 0; it < niter; it++) {
        const int b = it & 1;
        if (it + 1 < niter) { loadX(it+1); loadW(it+1); }
        const float* X = sX[b];
        const float* W = sW[b];
#pragma unroll
        for (int k = 0; k < KSTEP; k++) {
            float2 xv = *(const float2*)&X[k*66 + rg*2];
            float4 wv = *(const float4*)&W[k*36 + cg*4];
            a00 += xv.x*wv.x; a01 += xv.x*wv.y; a02 += xv.x*wv.z; a03 += xv.x*wv.w;
            a10 += xv.y*wv.x; a11 += xv.y*wv.y; a12 += xv.y*wv.z; a13 += xv.y*wv.w;
        }
        if (it + 1 < niter) {
            storeTiles(b ^ 1);
            __syncthreads();
        }
    }

    float4 bv = {0.f,0.f,0.f,0.f};
    if (split == 0 && gd.bias) bv = *(const float4*)(gd.bias + cb + cg*4);
    float* y = gd.y + (size_t)split*ND;
    float4 o0 = {a00+bv.x, a01+bv.y, a02+bv.z, a03+bv.w};
    float4 o1 = {a10+bv.x, a11+bv.y, a12+bv.z, a13+bv.w};
    *(float4*)(y + (rg*2+0)*DD + cb + cg*4) = o0;
    *(float4*)(y + (rg*2+1)*DD + cb + cg*4) = o1;

    // fused mem-combine: last of the 6 desc-blocks for this column tile finishes
    if (batch.docombine) {
        __threadfence();
        __shared__ int s_last;
        if (tid == 0) s_last = (atomicAdd(&g_cnt2[blockIdx.x], 1) == 5);
        __syncthreads();
        if (s_last) {
            __threadfence();
#pragma unroll
            for (int k = 0; k < 8; k++) {
                int idx = tid + k*256;           // 0..2047
                int nn = idx >> 5;
                int d  = cb + (idx & 31);
                float m1 = g_P[0*ND + nn*DD + d] + g_P[1*ND + nn*DD + d]
                         + g_P[2*ND + nn*DD + d] + batch.d1b[d];
                float m2 = g_P[3*ND + nn*DD + d] + g_P[4*ND + nn*DD + d]
                         + g_P[5*ND + nn*DD + d] + batch.d2b[d];
                float p0 = batch.mprob[nn*MM + 0];
                float p7 = batch.mprob[nn*MM + 7];
                float p8 = batch.mprob[nn*MM + 8];
                batch.outp[NB*HWS*LL + NB*LL + nn*DD + d] =
                    p0*batch.memprev[nn*DD + d] + p7*m1 + p8*m2;
            }
        }
    }
}

// ---------------- prep: per-n scalars + counter reset ----------------
__global__ __launch_bounds__(256) void prep_kernel(const float* __restrict__ module_prob,
                                                   const float* __restrict__ stack_ptr,
                                                   const float* __restrict__ find_kb,
                                                   const float* __restrict__ transform_kb,
                                                   float* __restrict__ out) {
    int n = blockIdx.x, tid = threadIdx.x;
    int lane = tid & 31, wid = tid >> 5;
    __shared__ float redA[8], redB[8];

    if (tid == 0) {
        g_cnt[n] = 0;
        if (n < 24) g_cnt2[n] = 0;
    }

    float s1 = 0.f, s2 = 0.f;
    for (int j = tid; j < DD; j += 256) {
        float qv = g_qf[n*DD+j] + g_qf[ND + n*DD+j] + g_qf[2*ND + n*DD+j];
        float tv = g_qt[n*DD+j] + g_qt[ND + n*DD+j] + g_qt[2*ND + n*DD+j];
        s1 += qv*find_kb[j]; s2 += tv*transform_kb[j];
    }
#pragma unroll
    for (int o = 16; o; o >>= 1) {
        s1 += __shfl_xor_sync(0xffffffffu, s1, o);
        s2 += __shfl_xor_sync(0xffffffffu, s2, o);
    }
    if (lane == 0) { redA[wid] = s1; redB[wid] = s2; }
    __syncthreads();
    if (tid == 0) {
        float S1 = 0.f, S2 = 0.f;
        for (int w = 0; w < 8; w++) { S1 += redA[w]; S2 += redB[w]; }
        g_biasf[n] = S1*FSCALE; g_biast[n] = S2*FSCALE;

        float ptr[LL], pfw[LL], pb[LL], pbfw[LL], p[MM];
        for (int l = 0; l < LL; l++) ptr[l] = stack_ptr[n*LL + l];
        for (int m = 0; m < MM; m++) p[m] = module_prob[n*MM + m];
        pfw[0] = 0.f;
        for (int l = 1; l < LL; l++) pfw[l] = ptr[l-1];
        pfw[LL-1] += ptr[LL-1];
        for (int l = 0; l < LL-1; l++) pb[l] = ptr[l+1];
        pb[LL-1] = 0.f; pb[0] += ptr[0];
        for (int l = 0; l < LL-1; l++) pbfw[l] = pfw[l+1];
        pbfw[LL-1] = 0.f; pbfw[0] += pfw[0];
        float A = 0.f, Bv = 0.f;
        for (int l = 0; l < LL; l++) { A += pfw[l]*pfw[l]; Bv += pfw[l]*pbfw[l]; }
        g_A[n] = A; g_B[n] = Bv;
        float pav[LL], mx = -1e30f;
        for (int l = 0; l < LL; l++) {
            pav[l] = (p[0]+p[2]+p[7])*ptr[l] + (p[1]+p[6])*pfw[l]
                   + p[3]*pbfw[l] + (p[4]+p[5]+p[8])*pb[l];
            mx = fmaxf(mx, pav[l]*10.0f);
        }
        float sm = 0.f, e[LL];
        for (int l = 0; l < LL; l++) { e[l] = expf(pav[l]*10.0f - mx); sm += e[l]; }
        for (int l = 0; l < LL; l++) out[NB*HWS*LL + n*LL + l] = e[l]/sm;
        for (int l = 0; l < LL; l++) {
            float c0 = p[0]+p[7]+p[8] + (p[1]+p[6])*(1.f-pfw[l]) + p[2]*(1.f-ptr[l])
                     + (p[4]+p[5])*(1.f-pb[l]) + p[3]*(1.f-pfw[l])*(1.f-pbfw[l]);
            g_coef[n*56 + 0*8 + l] = c0;
            g_coef[n*56 + 1*8 + l] = p[1]*pfw[l] + p[3]*pfw[l]*(1.f-pbfw[l]);
            g_coef[n*56 + 2*8 + l] = p[2]*ptr[l];
            g_coef[n*56 + 3*8 + l] = p[3]*pbfw[l];
            g_coef[n*56 + 4*8 + l] = p[4]*pb[l];
            g_coef[n*56 + 5*8 + l] = p[5]*pb[l];
            g_coef[n*56 + 6*8 + l] = p[6]*pfw[l];
            g_pvec[n*32 + l]      = pb[l];
            g_pvec[n*32 + 8 + l]  = pfw[l]*(1.f-pfw[l]);
            g_pvec[n*32 + 16 + l] = pbfw[l]*(1.f-pfw[l]);
            g_pvec[n*32 + 24 + l] = ptr[l];
        }
    }
}

// ---------------- image pass v3: fused attn + stream + extreduce ----------------
__global__ __launch_bounds__(256) void image_kernel(const float* __restrict__ image_hidden,
                                                    const float* __restrict__ image_mask,
                                                    const float* __restrict__ att_stack,
                                                    const float* __restrict__ scene_w,
                                                    const float* __restrict__ scene_b,
                                                    float* __restrict__ out) {
    const int n = blockIdx.y;
    const int chunk = blockIdx.x;
    const int tid = threadIdx.x, lane = tid & 31, w = tid >> 5;
    const int h = w & 1;
    const int g = w >> 1;

    __shared__ float eps1[4][768];
    __shared__ float eps2[4][768];
    __shared__ float sdots[128][8];
    __shared__ float satt[128][6];   // a1,a2,gg1,gg2,w1,w2
    __shared__ float s_pv[32];
    __shared__ float swsum[2][4];

    if (tid < 32) s_pv[tid] = g_pvec[n*32 + tid];
    __syncthreads();

    // per-row attention phase (threads 0..127, one row each)
    if (tid < 128) {
        const int s = chunk*128 + tid;
        const float* Sr = att_stack + ((size_t)n*HWS + s)*LL;
        float4 lo = *(const float4*)Sr;
        float4 hi = *(const float4*)(Sr+4);
        float S[8] = {lo.x,lo.y,lo.z,lo.w,hi.x,hi.y,hi.z,hi.w};
        float a1 = 0.f, a2 = 0.f, gg1 = 0.f, gg2 = 0.f;
#pragma unroll
        for (int l = 0; l < 8; l++) {
            a1 += S[l]*s_pv[l];      a2 += S[l]*s_pv[24+l];
            gg1 += S[l]*s_pv[8+l];   gg2 += S[l]*s_pv[16+l];
        }
        float w1 = expf(a1), w2 = expf(a2);
        satt[tid][0]=a1; satt[tid][1]=a2; satt[tid][2]=gg1; satt[tid][3]=gg2;
        satt[tid][4]=w1; satt[tid][5]=w2;
        float t1 = w1, t2 = w2;
#pragma unroll
        for (int o = 16; o; o >>= 1) {
            t1 += __shfl_xor_sync(0xffffffffu, t1, o);
            t2 += __shfl_xor_sync(0xffffffffu, t2, o);
        }
        if (lane == 0) { swsum[0][w] = t1; swsum[1][w] = t2; }
    }
    __syncthreads();
    if (tid == 0) {
        g_wsum1[n*NCH + chunk] = swsum[0][0]+swsum[0][1]+swsum[0][2]+swsum[0][3];
        g_wsum2[n*NCH + chunk] = swsum[1][0]+swsum[1][1]+swsum[1][2]+swsum[1][3];
    }

    const float4* q0 = (const float4*)(g_qkf + n*DD);
    const float4* q1 = (const float4*)(g_qkf + ND + n*DD);
    const float4* q2 = (const float4*)(g_qkf + 2*ND + n*DD);
    const float4* t0 = (const float4*)(g_qkt + n*DD);
    const float4* t1p = (const float4*)(g_qkt + ND + n*DD);
    const float4* t2p = (const float4*)(g_qkt + 2*ND + n*DD);
    const float4* sw4 = (const float4*)scene_w;

    const int base4 = h*96 + lane;
    float4 qkf[3], qkt[3], scw[3], e1[3], e2[3];
#pragma unroll
    for (int j = 0; j < 3; j++) {
        int idx = base4 + j*32;
        float4 a = q0[idx], b = q1[idx], c = q2[idx];
        qkf[j] = make_float4(a.x+b.x+c.x, a.y+b.y+c.y, a.z+b.z+c.z, a.w+b.w+c.w);
        a = t0[idx]; b = t1p[idx]; c = t2p[idx];
        qkt[j] = make_float4(a.x+b.x+c.x, a.y+b.y+c.y, a.z+b.z+c.z, a.w+b.w+c.w);
        scw[j] = sw4[idx];
        e1[j] = make_float4(0.f,0.f,0.f,0.f);
        e2[j] = make_float4(0.f,0.f,0.f,0.f);
    }

    const int row0 = chunk*128 + g*32;
    for (int rp = 0; rp < 16; rp++) {
        const int s0 = row0 + rp*2;
        const int s1 = s0 + 1;
        const int r0l = g*32 + rp*2;
        const float4* i0 = (const float4*)(image_hidden + ((size_t)n*HWS + s0)*DD) + base4;
        const float4* i1 = (const float4*)(image_hidden + ((size_t)n*HWS + s1)*DD) + base4;
        float4 v0[3], v1[3];
#pragma unroll
        for (int j = 0; j < 3; j++) v0[j] = __ldcs(i0 + j*32);
#pragma unroll
        for (int j = 0; j < 3; j++) v1[j] = __ldcs(i1 + j*32);

        float w1a = satt[r0l][4],   w2a = satt[r0l][5];
        float w1b = satt[r0l+1][4], w2b = satt[r0l+1][5];

        float n2a=0,dfa=0,dta=0,dsa=0,n2b=0,dfb=0,dtb=0,dsb=0;
#pragma unroll
        for (int j = 0; j < 3; j++) {
            float4 a = v0[j], b = v1[j];
            n2a += a.x*a.x + a.y*a.y + a.z*a.z + a.w*a.w;
            n2b += b.x*b.x + b.y*b.y + b.z*b.z + b.w*b.w;
            dfa += a.x*qkf[j].x + a.y*qkf[j].y + a.z*qkf[j].z + a.w*qkf[j].w;
            dfb += b.x*qkf[j].x + b.y*qkf[j].y + b.z*qkf[j].z + b.w*qkf[j].w;
            dta += a.x*qkt[j].x + a.y*qkt[j].y + a.z*qkt[j].z + a.w*qkt[j].w;
            dtb += b.x*qkt[j].x + b.y*qkt[j].y + b.z*qkt[j].z + b.w*qkt[j].w;
            dsa += a.x*scw[j].x + a.y*scw[j].y + a.z*scw[j].z + a.w*scw[j].w;
            dsb += b.x*scw[j].x + b.y*scw[j].y + b.z*scw[j].z + b.w*scw[j].w;
            e1[j].x += w1a*a.x + w1b*b.x; e1[j].y += w1a*a.y + w1b*b.y;
            e1[j].z += w1a*a.z + w1b*b.z; e1[j].w += w1a*a.w + w1b*b.w;
            e2[j].x += w2a*a.x + w2b*b.x; e2[j].y += w2a*a.y + w2b*b.y;
            e2[j].z += w2a*a.z + w2b*b.z; e2[j].w += w2a*a.w + w2b*b.w;
        }
#pragma unroll
        for (int o = 16; o; o >>= 1) {
            n2a += __shfl_xor_sync(0xffffffffu, n2a, o);
            n2b += __shfl_xor_sync(0xffffffffu, n2b, o);
            dfa += __shfl_xor_sync(0xffffffffu, dfa, o);
            dfb += __shfl_xor_sync(0xffffffffu, dfb, o);
            dta += __shfl_xor_sync(0xffffffffu, dta, o);
            dtb += __shfl_xor_sync(0xffffffffu, dtb, o);
            dsa += __shfl_xor_sync(0xffffffffu, dsa, o);
            dsb += __shfl_xor_sync(0xffffffffu, dsb, o);
        }
        if (lane == 0) {
            sdots[r0l][h*4+0] = n2a; sdots[r0l][h*4+1] = dfa;
            sdots[r0l][h*4+2] = dta; sdots[r0l][h*4+3] = dsa;
            sdots[r0l+1][h*4+0] = n2b; sdots[r0l+1][h*4+1] = dfb;
            sdots[r0l+1][h*4+2] = dtb; sdots[r0l+1][h*4+3] = dsb;
        }
    }
    {
        float4* d1 = (float4*)&eps1[g][h*384];
        float4* d2 = (float4*)&eps2[g][h*384];
#pragma unroll
        for (int j = 0; j < 3; j++) {
            d1[lane + j*32] = e1[j];
            d2[lane + j*32] = e2[j];
        }
    }
    __syncthreads();

    // e-partials to global
#pragma unroll
    for (int u = 0; u < 6; u++) {
        int idx = tid + u*256;
        int e = (idx >= 768) ? 1 : 0;
        int d = idx - e*768;
        float sum;
        if (e == 0) sum = eps1[0][d] + eps1[1][d] + eps1[2][d] + eps1[3][d];
        else        sum = eps2[0][d] + eps2[1][d] + eps2[2][d] + eps2[3][d];
        g_extpart[((e*NCH) + chunk)*NB*DD + n*DD + d] = sum;
    }

    // score phase: 2 threads per row
    {
        const int r = tid >> 1;
        const int sub = tid & 1;
        const int s = chunk*128 + r;
        float n2 = sdots[r][0] + sdots[r][4];
        float df = sdots[r][1] + sdots[r][5];
        float dt = sdots[r][2] + sdots[r][6];
        float dsc = sdots[r][3] + sdots[r][7];
        float biasf = g_biasf[n], biast = g_biast[n];
        float Av = g_A[n], Bv = g_B[n], scb = scene_b[0];
        float inv = 1.0f / fmaxf(sqrtf(n2), FEPS);
        float mk = image_mask[n*HWS + s];
        float sf = df*inv*FSCALE + biasf + mk;
        float st = dt*inv*FSCALE + biast + mk;
        float sc = dsc + scb;
        float a1 = satt[r][0], a2 = satt[r][1];
        float gg1 = satt[r][2], gg2 = satt[r][3];
        float a2f = sf*Av + gg1;
        float a1f = sf*Bv + gg2;
        float mf = fminf(a1f, a2f);
        float mn = fminf(a1, a2);
        float mx = fmaxf(a1, a2);
        const float* cf = g_coef + n*56 + sub*4;
        float4 K0 = *(const float4*)(cf + 0);
        float4 K1 = *(const float4*)(cf + 8);
        float4 K2 = *(const float4*)(cf + 16);
        float4 K3 = *(const float4*)(cf + 24);
        float4 K4 = *(const float4*)(cf + 32);
        float4 K5 = *(const float4*)(cf + 40);
        float4 K6 = *(const float4*)(cf + 48);
        float4 Sv = *(const float4*)(att_stack + ((size_t)n*HWS + s)*LL + sub*4);
        float4 o;
        o.x = Sv.x*K0.x + sf*K1.x + st*K2.x + mf*K3.x + mn*K4.x + mx*K5.x + sc*K6.x;
        o.y = Sv.y*K0.y + sf*K1.y + st*K2.y + mf*K3.y + mn*K4.y + mx*K5.y + sc*K6.y;
        o.z = Sv.z*K0.z + sf*K1.z + st*K2.z + mf*K3.z + mn*K4.z + mx*K5.z + sc*K6.z;
        o.w = Sv.w*K0.w + sf*K1.w + st*K2.w + mf*K3.w + mn*K4.w + mx*K5.w + sc*K6.w;
        *(float4*)(out + ((size_t)n*HWS + s)*LL + sub*4) = o;
    }

    // fused extreduce: last block for this n
    __threadfence();
    __shared__ int s_last;
    if (tid == 0) s_last = (atomicAdd(&g_cnt[n], 1) == NCH-1);
    __syncthreads();
    if (s_last) {
        __threadfence();
        float T1 = 0.f, T2 = 0.f;
#pragma unroll
        for (int c = 0; c < NCH; c++) { T1 += g_wsum1[n*NCH+c]; T2 += g_wsum2[n*NCH+c]; }
        float inv1 = 1.0f / T1, inv2 = 1.0f / T2;
#pragma unroll
        for (int u = 0; u < 3; u++) {
            int d = tid + u*256;
            float e1s = 0.f, e2s = 0.f;
#pragma unroll
            for (int c = 0; c < NCH; c++) {
                e1s += g_extpart[(0*NCH + c)*NB*DD + n*DD + d];
                e2s += g_extpart[(1*NCH + c)*NB*DD + n*DD + d];
            }
            e1s *= inv1; e2s *= inv2;
            float c1v = g_c1[n*DD + d] + g_c1[ND + n*DD + d] + g_c1[2*ND + n*DD + d];
            float c2v = g_c2[n*DD + d] + g_c2[ND + n*DD + d] + g_c2[2*ND + n*DD + d];
            g_e2[n*DD + d]   = e2s;
            g_e2c1[n*DD + d] = e2s*c1v;
            g_e1c2[n*DD + d] = e1s*c2v;
            g_e2c2[n*DD + d] = e2s*c2v;
        }
    }
}

// ---------------- launch ----------------
extern "C" void kernel_launch(void* const* d_in, const int* in_sizes, int n_in,
                              void* d_out, int out_size) {
    (void)in_sizes; (void)n_in; (void)out_size;
    const float* control   = (const float*)d_in[0];
    const float* mprob     = (const float*)d_in[1];
    const float* mem_prev  = (const float*)d_in[2];
    const float* att_stack = (const float*)d_in[3];
    const float* stack_ptr = (const float*)d_in[4];
    const float* image_h   = (const float*)d_in[8];
    const float* image_m   = (const float*)d_in[9];
    const float* find_ci_w = (const float*)d_in[10];
    const float* find_ci_b = (const float*)d_in[11];
    const float* find_q_w  = (const float*)d_in[12];
    const float* find_q_b  = (const float*)d_in[13];
    const float* find_k_w  = (const float*)d_in[14];
    const float* find_k_b  = (const float*)d_in[15];
    const float* tr_ci_w   = (const float*)d_in[16];
    const float* tr_ci_b   = (const float*)d_in[17];
    const float* tr_q_w    = (const float*)d_in[18];
    const float* tr_q_b    = (const float*)d_in[19];
    const float* tr_k_w    = (const float*)d_in[20];
    const float* tr_k_b    = (const float*)d_in[21];
    const float* scene_w   = (const float*)d_in[22];
    const float* scene_b   = (const float*)d_in[23];
    const float* d1_ci_w   = (const float*)d_in[24];
    const float* d1_ci_b   = (const float*)d_in[25];
    const float* d1_mem_w  = (const float*)d_in[26];
    const float* d1_mem_b  = (const float*)d_in[27];
    const float* d2_ci_w   = (const float*)d_in[28];
    const float* d2_ci_b   = (const float*)d_in[29];
    const float* d2_mem_w  = (const float*)d_in[30];
    const float* d2_mem_b  = (const float*)d_in[31];
    float* out = (float*)d_out;

    float *p_cf, *p_ct, *p_c1, *p_c2, *p_qf, *p_qt, *p_qkf, *p_qkt;
    float *p_e2, *p_e2c1, *p_e1c2, *p_e2c2, *p_P;
    cudaGetSymbolAddress((void**)&p_cf,  g_cf);
    cudaGetSymbolAddress((void**)&p_ct,  g_ct);
    cudaGetSymbolAddress((void**)&p_c1,  g_c1);
    cudaGetSymbolAddress((void**)&p_c2,  g_c2);
    cudaGetSymbolAddress((void**)&p_qf,  g_qf);
    cudaGetSymbolAddress((void**)&p_qt,  g_qt);
    cudaGetSymbolAddress((void**)&p_qkf, g_qkf);
    cudaGetSymbolAddress((void**)&p_qkt, g_qkt);
    cudaGetSymbolAddress((void**)&p_e2,  g_e2);
    cudaGetSymbolAddress((void**)&p_e2c1, g_e2c1);
    cudaGetSymbolAddress((void**)&p_e1c2, g_e1c2);
    cudaGetSymbolAddress((void**)&p_e2c2, g_e2c2);
    cudaGetSymbolAddress((void**)&p_P,   g_P);

    G2Batch b1 = {};
    b1.nsplit = SPL; b1.nx = 1; b1.docombine = 0;
    b1.d[0] = {control, nullptr, nullptr, find_ci_w, find_ci_b, p_cf, 0};
    b1.d[1] = {control, nullptr, nullptr, tr_ci_w,   tr_ci_b,   p_ct, 0};
    b1.d[2] = {control, nullptr, nullptr, d1_ci_w,   d1_ci_b,   p_c1, 0};
    b1.d[3] = {control, nullptr, nullptr, d2_ci_w,   d2_ci_b,   p_c2, 0};
    gemm3_kernel<<<dim3(24,4,SPL), 256>>>(b1);

    G2Batch b2 = {};
    b2.nsplit = SPL; b2.nx = 3; b2.docombine = 0;
    b2.d[0] = {p_cf, p_cf+ND, p_cf+2*ND, find_q_w, find_q_b, p_qf, 0};
    b2.d[1] = {p_ct, p_ct+ND, p_ct+2*ND, tr_q_w,   tr_q_b,   p_qt, 0};
    gemm3_kernel<<<dim3(24,2,SPL), 256>>>(b2);

    prep_kernel<<<NB, 256>>>(mprob, stack_ptr, find_k_b, tr_k_b, out);

    G2Batch b3 = {};
    b3.nsplit = SPL; b3.nx = 3; b3.docombine = 0;
    b3.d[0] = {p_qf, p_qf+ND, p_qf+2*ND, find_k_w, nullptr, p_qkf, 1};
    b3.d[1] = {p_qt, p_qt+ND, p_qt+2*ND, tr_k_w,   nullptr, p_qkt, 1};
    gemm3_kernel<<<dim3(24,2,SPL), 256>>>(b3);

    image_kernel<<<dim3(NCH, NB), 256>>>(image_h, image_m, att_stack, scene_w, scene_b, out);

    G2Batch b4 = {};
    b4.nsplit = 1; b4.nx = 1; b4.docombine = 1;
    b4.mprob = mprob; b4.memprev = mem_prev; b4.d1b = d1_mem_b; b4.d2b = d2_mem_b; b4.outp = out;
    b4.d[0] = {control, nullptr, nullptr, d1_mem_w,             nullptr, p_P + 0*ND, 0};
    b4.d[1] = {p_e2,    nullptr, nullptr, d1_mem_w + DD*DD,     nullptr, p_P + 1*ND, 0};
    b4.d[2] = {p_e2c1,  nullptr, nullptr, d1_mem_w + 2*DD*DD,   nullptr, p_P + 2*ND, 0};
    b4.d[3] = {control, nullptr, nullptr, d2_mem_w,             nullptr, p_P + 3*ND, 0};
    b4.d[4] = {p_e1c2,  nullptr, nullptr, d2_mem_w + DD*DD,     nullptr, p_P + 4*ND, 0};
    b4.d[5] = {p_e2c2,  nullptr, nullptr, d2_mem_w + 2*DD*DD,   nullptr, p_P + 5*ND, 0};
    gemm3_kernel<<<dim3(24,6,1), 256>>>(b4);
}